// round 1
// baseline (speedup 1.0000x reference)
#include <cuda_runtime.h>
#include <cuda_bf16.h>

// Problem constants
#define BATCH 2
#define SEQ   2048
#define DIMM  1024
#define NH    16
#define HD    64
#define NP    257      // 2*128+1 relative positions
#define RREL  128
#define RADIUS 256

// ---------------------------------------------------------------------------
// Device scratch (static allocations only — no cudaMalloc allowed)
// ---------------------------------------------------------------------------
__device__ float g_q[BATCH * SEQ * DIMM];                  // projected Q  [b,s,h*64+d]
__device__ float g_k[BATCH * SEQ * DIMM];                  // projected K
__device__ float g_v[BATCH * SEQ * DIMM];                  // projected V
__device__ float g_ctx[BATCH * SEQ * DIMM];                // attention output [b,s,h*64+d]
__device__ float g_relT[NH * NP * HD];                     // rel[h,p,d] = E[p, d*16+h]
__device__ float g_qrel[(size_t)BATCH * NH * SEQ * NP];    // q . rel  [b,h,s,p]
__device__ float g_wop[DIMM * DIMM];                       // permuted Wo

// ---------------------------------------------------------------------------
// Standard SGEMM: C[M,N] = A[M,K] @ W[N,K]^T   (row-major, all dims % 128 == 0
// except K which is % 8). BM=BN=128, BK=8, 256 threads, 8x8 per thread.
// ---------------------------------------------------------------------------
__global__ __launch_bounds__(256) void sgemm_nt(
    const float* __restrict__ A, const float* __restrict__ W,
    float* __restrict__ C, int M, int N, int K)
{
    __shared__ float As[8][128];
    __shared__ float Bs[8][128];

    const int tid = threadIdx.x;
    const int tx = tid & 15, ty = tid >> 4;
    const int m0 = blockIdx.y * 128, n0 = blockIdx.x * 128;

    const int lrow = tid >> 1;          // 0..127
    const int lk   = (tid & 1) * 4;     // 0 or 4

    const float* Ap = A + (size_t)(m0 + lrow) * K + lk;
    const float* Wp = W + (size_t)(n0 + lrow) * K + lk;

    float acc[8][8];
    #pragma unroll
    for (int i = 0; i < 8; i++)
        #pragma unroll
        for (int j = 0; j < 8; j++) acc[i][j] = 0.f;

    float4 av = *(const float4*)(Ap);
    float4 bv = *(const float4*)(Wp);

    for (int k0 = 0; k0 < K; k0 += 8) {
        As[lk + 0][lrow] = av.x; As[lk + 1][lrow] = av.y;
        As[lk + 2][lrow] = av.z; As[lk + 3][lrow] = av.w;
        Bs[lk + 0][lrow] = bv.x; Bs[lk + 1][lrow] = bv.y;
        Bs[lk + 2][lrow] = bv.z; Bs[lk + 3][lrow] = bv.w;
        __syncthreads();

        if (k0 + 8 < K) {
            av = *(const float4*)(Ap + k0 + 8);
            bv = *(const float4*)(Wp + k0 + 8);
        }

        #pragma unroll
        for (int k = 0; k < 8; k++) {
            float a[8], bb[8];
            *(float4*)&a[0]  = *(const float4*)&As[k][ty * 8];
            *(float4*)&a[4]  = *(const float4*)&As[k][ty * 8 + 4];
            *(float4*)&bb[0] = *(const float4*)&Bs[k][tx * 8];
            *(float4*)&bb[4] = *(const float4*)&Bs[k][tx * 8 + 4];
            #pragma unroll
            for (int i = 0; i < 8; i++)
                #pragma unroll
                for (int j = 0; j < 8; j++)
                    acc[i][j] += a[i] * bb[j];
        }
        __syncthreads();
    }

    #pragma unroll
    for (int i = 0; i < 8; i++) {
        float* crow = C + (size_t)(m0 + ty * 8 + i) * N + n0 + tx * 8;
        #pragma unroll
        for (int j = 0; j < 8; j++) crow[j] = acc[i][j];
    }
}

// ---------------------------------------------------------------------------
// relT[h,p,d] = E[p, d*16 + h]
// ---------------------------------------------------------------------------
__global__ void relT_kernel(const float* __restrict__ E)
{
    int idx = blockIdx.x * 256 + threadIdx.x;
    if (idx < NH * NP * HD) {
        int d = idx & 63;
        int p = (idx >> 6) % NP;
        int h = idx / (NP * HD);
        g_relT[idx] = E[(size_t)p * DIMM + d * NH + h];
    }
}

// ---------------------------------------------------------------------------
// WoP[n,k] = Wo[n, (k%64)*16 + k/64]   (folds the head-merge permute)
// ---------------------------------------------------------------------------
__global__ void wop_kernel(const float* __restrict__ Wo)
{
    int idx = blockIdx.x * 256 + threadIdx.x;
    if (idx < DIMM * DIMM) {
        int k = idx & 1023;
        int n = idx >> 10;
        g_wop[idx] = Wo[(size_t)n * DIMM + (k & 63) * NH + (k >> 6)];
    }
}

// ---------------------------------------------------------------------------
// qrel[b,h,s,p] = sum_d q[b,h,s,d] * relT[h,p,d]
// grid (SEQ/64, NH, BATCH), 256 threads, 4x4 per thread per 64x64 subtile.
// ---------------------------------------------------------------------------
__global__ __launch_bounds__(256) void qrel_kernel(const float* __restrict__ Qp)
{
    __shared__ float QsT[64][68];  // [d][s]
    __shared__ float RsT[64][68];  // [d][p]

    const int i0 = blockIdx.x * 64;
    const int h = blockIdx.y, b = blockIdx.z;
    const int tid = threadIdx.x, tx = tid & 15, ty = tid >> 4;

    const size_t qbase = ((size_t)b * SEQ) * DIMM + h * HD;
    for (int idx = tid; idx < 64 * 64; idx += 256) {
        int r = idx >> 6, d = idx & 63;
        QsT[d][r] = Qp[qbase + (size_t)(i0 + r) * DIMM + d];
    }

    float* orow = g_qrel + (((size_t)b * NH + h) * SEQ + i0) * NP;

    for (int p0 = 0; p0 < NP; p0 += 64) {
        __syncthreads();
        for (int idx = tid; idx < 64 * 64; idx += 256) {
            int pp = idx >> 6, d = idx & 63;
            int p = p0 + pp;
            RsT[d][pp] = (p < NP) ? g_relT[((size_t)h * NP + p) * HD + d] : 0.f;
        }
        __syncthreads();

        float acc[4][4];
        #pragma unroll
        for (int i = 0; i < 4; i++)
            #pragma unroll
            for (int j = 0; j < 4; j++) acc[i][j] = 0.f;

        #pragma unroll 16
        for (int d = 0; d < 64; d++) {
            float4 a4 = *(const float4*)&QsT[d][ty * 4];
            float4 b4 = *(const float4*)&RsT[d][tx * 4];
            acc[0][0] += a4.x * b4.x; acc[0][1] += a4.x * b4.y; acc[0][2] += a4.x * b4.z; acc[0][3] += a4.x * b4.w;
            acc[1][0] += a4.y * b4.x; acc[1][1] += a4.y * b4.y; acc[1][2] += a4.y * b4.z; acc[1][3] += a4.y * b4.w;
            acc[2][0] += a4.z * b4.x; acc[2][1] += a4.z * b4.y; acc[2][2] += a4.z * b4.z; acc[2][3] += a4.z * b4.w;
            acc[3][0] += a4.w * b4.x; acc[3][1] += a4.w * b4.y; acc[3][2] += a4.w * b4.z; acc[3][3] += a4.w * b4.w;
        }

        #pragma unroll
        for (int i = 0; i < 4; i++) {
            #pragma unroll
            for (int j = 0; j < 4; j++) {
                int p = p0 + tx * 4 + j;
                if (p < NP)
                    orow[(size_t)(ty * 4 + i) * NP + p] = acc[i][j];
            }
        }
    }
}

// ---------------------------------------------------------------------------
// Banded flash attention with relative-position bias.
// TQ=64 queries per block, TK=32 keys per tile, window |j-i| <= 256.
// grid (SEQ/64, NH, BATCH), 256 threads (16x16): S-tile 4x2, O-tile 4x4.
// Writes ctx[b, s, h*64+d].
// ---------------------------------------------------------------------------
__global__ __launch_bounds__(256) void attn_kernel(
    const float* __restrict__ Qp, const float* __restrict__ Kp,
    const float* __restrict__ Vp, float* __restrict__ CTX)
{
    __shared__ float Qt[64][68];   // [d][r]
    __shared__ float Kt[64][34];   // [d][c]
    __shared__ float Vs[32][68];   // [c][d]
    __shared__ float PsT[32][68];  // [c][r]
    __shared__ float red[64][17];

    const int i0 = blockIdx.x * 64;
    const int h = blockIdx.y, b = blockIdx.z;
    const int tid = threadIdx.x, tx = tid & 15, ty = tid >> 4;

    const size_t base = ((size_t)b * SEQ) * DIMM + h * HD;

    for (int idx = tid; idx < 64 * 64; idx += 256) {
        int r = idx >> 6, d = idx & 63;
        Qt[d][r] = Qp[base + (size_t)(i0 + r) * DIMM + d];
    }

    float mrow[4], lrow[4], O[4][4];
    #pragma unroll
    for (int i = 0; i < 4; i++) {
        mrow[i] = -1e30f; lrow[i] = 0.f;
        #pragma unroll
        for (int j = 0; j < 4; j++) O[i][j] = 0.f;
    }

    const float* qrl = g_qrel + (((size_t)b * NH + h) * SEQ) * NP;

    int jstart = i0 - RADIUS; if (jstart < 0) jstart = 0;
    int jend = i0 + 64 + RADIUS; if (jend > SEQ) jend = SEQ;

    __syncthreads();

    for (int j0 = jstart; j0 < jend; j0 += 32) {
        // load K,V tiles
        for (int idx = tid; idx < 32 * 64; idx += 256) {
            int c = idx >> 6, d = idx & 63;
            size_t g = base + (size_t)(j0 + c) * DIMM + d;
            Kt[d][c] = Kp[g];
            Vs[c][d] = Vp[g];
        }
        __syncthreads();

        // S = Q K^T
        float s[4][2];
        #pragma unroll
        for (int i = 0; i < 4; i++) { s[i][0] = 0.f; s[i][1] = 0.f; }

        #pragma unroll 16
        for (int d = 0; d < 64; d++) {
            float4 a4 = *(const float4*)&Qt[d][ty * 4];
            float2 b2 = *(const float2*)&Kt[d][tx * 2];
            s[0][0] += a4.x * b2.x; s[0][1] += a4.x * b2.y;
            s[1][0] += a4.y * b2.x; s[1][1] += a4.y * b2.y;
            s[2][0] += a4.z * b2.x; s[2][1] += a4.z * b2.y;
            s[3][0] += a4.w * b2.x; s[3][1] += a4.w * b2.y;
        }

        // rel bias + mask + scale
        #pragma unroll
        for (int i = 0; i < 4; i++) {
            const int gi = i0 + ty * 4 + i;
            #pragma unroll
            for (int j = 0; j < 2; j++) {
                const int gj = j0 + tx * 2 + j;
                const int dl = gj - gi;
                if (dl > RADIUS || dl < -RADIUS) {
                    s[i][j] = -1e30f;
                } else {
                    int p = dl; if (p > RREL) p = RREL; if (p < -RREL) p = -RREL;
                    s[i][j] = (s[i][j] + qrl[(size_t)gi * NP + p + RREL]) * 0.125f;
                }
            }
        }

        // online softmax: row max
        #pragma unroll
        for (int i = 0; i < 4; i++)
            red[ty * 4 + i][tx] = fmaxf(s[i][0], s[i][1]);
        __syncthreads();

        float scl[4], psum[4];
        #pragma unroll
        for (int i = 0; i < 4; i++) {
            float rm = -1e30f;
            #pragma unroll
            for (int t = 0; t < 16; t++) rm = fmaxf(rm, red[ty * 4 + i][t]);
            float mn = fmaxf(mrow[i], rm);
            scl[i] = __expf(mrow[i] - mn);
            mrow[i] = mn;
            float p0 = __expf(s[i][0] - mn);
            float p1 = __expf(s[i][1] - mn);
            s[i][0] = p0; s[i][1] = p1;
            psum[i] = p0 + p1;
        }
        __syncthreads();   // done reading red (max pass)

        #pragma unroll
        for (int i = 0; i < 4; i++) {
            red[ty * 4 + i][tx] = psum[i];
            PsT[tx * 2 + 0][ty * 4 + i] = s[i][0];
            PsT[tx * 2 + 1][ty * 4 + i] = s[i][1];
        }
        __syncthreads();

        #pragma unroll
        for (int i = 0; i < 4; i++) {
            float rs = 0.f;
            #pragma unroll
            for (int t = 0; t < 16; t++) rs += red[ty * 4 + i][t];
            lrow[i] = lrow[i] * scl[i] + rs;
            #pragma unroll
            for (int j = 0; j < 4; j++) O[i][j] *= scl[i];
        }

        // O += P V
        #pragma unroll 8
        for (int c = 0; c < 32; c++) {
            float4 a4 = *(const float4*)&PsT[c][ty * 4];
            float4 b4 = *(const float4*)&Vs[c][tx * 4];
            O[0][0] += a4.x * b4.x; O[0][1] += a4.x * b4.y; O[0][2] += a4.x * b4.z; O[0][3] += a4.x * b4.w;
            O[1][0] += a4.y * b4.x; O[1][1] += a4.y * b4.y; O[1][2] += a4.y * b4.z; O[1][3] += a4.y * b4.w;
            O[2][0] += a4.z * b4.x; O[2][1] += a4.z * b4.y; O[2][2] += a4.z * b4.z; O[2][3] += a4.z * b4.w;
            O[3][0] += a4.w * b4.x; O[3][1] += a4.w * b4.y; O[3][2] += a4.w * b4.z; O[3][3] += a4.w * b4.w;
        }
        __syncthreads();   // protect Kt/Vs/PsT/red before next tile
    }

    #pragma unroll
    for (int i = 0; i < 4; i++) {
        float inv = 1.f / lrow[i];
        float4 ov = make_float4(O[i][0] * inv, O[i][1] * inv, O[i][2] * inv, O[i][3] * inv);
        *(float4*)&CTX[base + (size_t)(i0 + ty * 4 + i) * DIMM + tx * 4] = ov;
    }
}

// ---------------------------------------------------------------------------
// Launch
// ---------------------------------------------------------------------------
extern "C" void kernel_launch(void* const* d_in, const int* in_sizes, int n_in,
                              void* d_out, int out_size)
{
    const float* Q  = (const float*)d_in[0];
    const float* K  = (const float*)d_in[1];
    const float* V  = (const float*)d_in[2];
    const float* Wq = (const float*)d_in[3];
    const float* Wk = (const float*)d_in[4];
    const float* Wv = (const float*)d_in[5];
    const float* Wo = (const float*)d_in[6];
    const float* E  = (const float*)d_in[7];
    float* out = (float*)d_out;

    float *q, *k, *v, *ctx, *wop;
    cudaGetSymbolAddress((void**)&q,   g_q);
    cudaGetSymbolAddress((void**)&k,   g_k);
    cudaGetSymbolAddress((void**)&v,   g_v);
    cudaGetSymbolAddress((void**)&ctx, g_ctx);
    cudaGetSymbolAddress((void**)&wop, g_wop);

    const int M = BATCH * SEQ;            // 4096
    dim3 gemm_grid(DIMM / 128, M / 128);  // (8, 32)

    // projections
    sgemm_nt<<<gemm_grid, 256>>>(Q, Wq, q, M, DIMM, DIMM);
    sgemm_nt<<<gemm_grid, 256>>>(K, Wk, k, M, DIMM, DIMM);
    sgemm_nt<<<gemm_grid, 256>>>(V, Wv, v, M, DIMM, DIMM);

    // permutes
    relT_kernel<<<(NH * NP * HD + 255) / 256, 256>>>(E);
    wop_kernel<<<(DIMM * DIMM) / 256, 256>>>(Wo);

    // relative-position logits
    qrel_kernel<<<dim3(SEQ / 64, NH, BATCH), 256>>>(q);

    // banded attention
    attn_kernel<<<dim3(SEQ / 64, NH, BATCH), 256>>>(q, k, v, ctx);

    // output projection (with permuted Wo)
    sgemm_nt<<<gemm_grid, 256>>>(ctx, wop, out, M, DIMM, DIMM);
}

// round 2
// speedup vs baseline: 1.0220x; 1.0220x over previous
#include <cuda_runtime.h>
#include <cuda_bf16.h>

// Problem constants
#define BATCH 2
#define SEQ   2048
#define DIMM  1024
#define NH    16
#define HD    64
#define NP    257      // 2*128+1 relative positions
#define RREL  128
#define RADIUS 256

typedef unsigned long long ull;

// ---------------------------------------------------------------------------
// Packed f32x2 helpers (sm_103a FFMA2 — only reachable via PTX)
// ---------------------------------------------------------------------------
__device__ __forceinline__ ull pack2(float x, float y) {
    ull r;
    asm("mov.b64 %0, {%1, %2};" : "=l"(r) : "f"(x), "f"(y));
    return r;
}
__device__ __forceinline__ float2 unpack2(ull v) {
    float2 r;
    asm("mov.b64 {%0, %1}, %2;" : "=f"(r.x), "=f"(r.y) : "l"(v));
    return r;
}
__device__ __forceinline__ ull fma2(ull a, ull b, ull c) {
    ull d;
    asm("fma.rn.f32x2 %0, %1, %2, %3;" : "=l"(d) : "l"(a), "l"(b), "l"(c));
    return d;
}
__device__ __forceinline__ ull mul2(ull a, ull b) {
    ull d;
    asm("mul.rn.f32x2 %0, %1, %2;" : "=l"(d) : "l"(a), "l"(b));
    return d;
}

// ---------------------------------------------------------------------------
// Device scratch (static allocations only — no cudaMalloc allowed)
// ---------------------------------------------------------------------------
__device__ float g_q[BATCH * SEQ * DIMM];                  // projected Q  [b,s,h*64+d]
__device__ float g_k[BATCH * SEQ * DIMM];                  // projected K
__device__ float g_v[BATCH * SEQ * DIMM];                  // projected V
__device__ float g_ctx[BATCH * SEQ * DIMM];                // attention output
__device__ float g_relT[NH * NP * HD];                     // rel[h,p,d] = E[p, d*16+h]
__device__ float g_qrel[(size_t)BATCH * NH * SEQ * NP];    // q . rel  [b,h,s,p]
__device__ float g_wop[DIMM * DIMM];                       // permuted Wo

// ---------------------------------------------------------------------------
// SGEMM: C[M,N] = A[M,K] @ W[N,K]^T  — BM=BN=128, BK=8, 256 thr, 8x8/thr,
// FFMA2 inner loop (32 fma2 + 12 packs vs 64 FFMA).
// ---------------------------------------------------------------------------
__global__ __launch_bounds__(256) void sgemm_nt(
    const float* __restrict__ A, const float* __restrict__ W,
    float* __restrict__ C, int M, int N, int K)
{
    __shared__ float As[8][128];
    __shared__ float Bs[8][128];

    const int tid = threadIdx.x;
    const int tx = tid & 15, ty = tid >> 4;
    const int m0 = blockIdx.y * 128, n0 = blockIdx.x * 128;

    const int lrow = tid >> 1;          // 0..127
    const int lk   = (tid & 1) * 4;     // 0 or 4

    const float* Ap = A + (size_t)(m0 + lrow) * K + lk;
    const float* Wp = W + (size_t)(n0 + lrow) * K + lk;

    ull acc[8][4];
    #pragma unroll
    for (int i = 0; i < 8; i++)
        #pragma unroll
        for (int j = 0; j < 4; j++) acc[i][j] = 0ull;

    float4 av = *(const float4*)(Ap);
    float4 bv = *(const float4*)(Wp);

    for (int k0 = 0; k0 < K; k0 += 8) {
        As[lk + 0][lrow] = av.x; As[lk + 1][lrow] = av.y;
        As[lk + 2][lrow] = av.z; As[lk + 3][lrow] = av.w;
        Bs[lk + 0][lrow] = bv.x; Bs[lk + 1][lrow] = bv.y;
        Bs[lk + 2][lrow] = bv.z; Bs[lk + 3][lrow] = bv.w;
        __syncthreads();

        if (k0 + 8 < K) {
            av = *(const float4*)(Ap + k0 + 8);
            bv = *(const float4*)(Wp + k0 + 8);
        }

        #pragma unroll
        for (int k = 0; k < 8; k++) {
            float4 a0 = *(const float4*)&As[k][ty * 8];
            float4 a1 = *(const float4*)&As[k][ty * 8 + 4];
            float4 b0 = *(const float4*)&Bs[k][tx * 8];
            float4 b1 = *(const float4*)&Bs[k][tx * 8 + 4];

            ull bp[4];
            bp[0] = pack2(b0.x, b0.y); bp[1] = pack2(b0.z, b0.w);
            bp[2] = pack2(b1.x, b1.y); bp[3] = pack2(b1.z, b1.w);

            float a[8] = {a0.x, a0.y, a0.z, a0.w, a1.x, a1.y, a1.z, a1.w};
            #pragma unroll
            for (int i = 0; i < 8; i++) {
                ull ap = pack2(a[i], a[i]);
                acc[i][0] = fma2(ap, bp[0], acc[i][0]);
                acc[i][1] = fma2(ap, bp[1], acc[i][1]);
                acc[i][2] = fma2(ap, bp[2], acc[i][2]);
                acc[i][3] = fma2(ap, bp[3], acc[i][3]);
            }
        }
        __syncthreads();
    }

    #pragma unroll
    for (int i = 0; i < 8; i++) {
        float* crow = C + (size_t)(m0 + ty * 8 + i) * N + n0 + tx * 8;
        float2 c0 = unpack2(acc[i][0]), c1 = unpack2(acc[i][1]);
        float2 c2 = unpack2(acc[i][2]), c3 = unpack2(acc[i][3]);
        *(float4*)(crow)     = make_float4(c0.x, c0.y, c1.x, c1.y);
        *(float4*)(crow + 4) = make_float4(c2.x, c2.y, c3.x, c3.y);
    }
}

// ---------------------------------------------------------------------------
// relT[h,p,d] = E[p, d*16 + h]
// ---------------------------------------------------------------------------
__global__ void relT_kernel(const float* __restrict__ E)
{
    int idx = blockIdx.x * 256 + threadIdx.x;
    if (idx < NH * NP * HD) {
        int d = idx & 63;
        int p = (idx >> 6) % NP;
        int h = idx / (NP * HD);
        g_relT[idx] = E[(size_t)p * DIMM + d * NH + h];
    }
}

// ---------------------------------------------------------------------------
// WoP[n,k] = Wo[n, (k%64)*16 + k/64]
// ---------------------------------------------------------------------------
__global__ void wop_kernel(const float* __restrict__ Wo)
{
    int idx = blockIdx.x * 256 + threadIdx.x;
    if (idx < DIMM * DIMM) {
        int k = idx & 1023;
        int n = idx >> 10;
        g_wop[idx] = Wo[(size_t)n * DIMM + (k & 63) * NH + (k >> 6)];
    }
}

// ---------------------------------------------------------------------------
// qrel[b,h,s,p] = sum_d q[b,h,s,d] * relT[h,p,d]  (FFMA2 inner loop)
// ---------------------------------------------------------------------------
__global__ __launch_bounds__(256) void qrel_kernel(const float* __restrict__ Qp)
{
    __shared__ float QsT[64][68];  // [d][s]
    __shared__ float RsT[64][68];  // [d][p]

    const int i0 = blockIdx.x * 64;
    const int h = blockIdx.y, b = blockIdx.z;
    const int tid = threadIdx.x, tx = tid & 15, ty = tid >> 4;

    const size_t qbase = ((size_t)b * SEQ) * DIMM + h * HD;
    for (int idx = tid; idx < 64 * 64; idx += 256) {
        int r = idx >> 6, d = idx & 63;
        QsT[d][r] = Qp[qbase + (size_t)(i0 + r) * DIMM + d];
    }

    float* orow = g_qrel + (((size_t)b * NH + h) * SEQ + i0) * NP;

    for (int p0 = 0; p0 < NP; p0 += 64) {
        __syncthreads();
        for (int idx = tid; idx < 64 * 64; idx += 256) {
            int pp = idx >> 6, d = idx & 63;
            int p = p0 + pp;
            RsT[d][pp] = (p < NP) ? g_relT[((size_t)h * NP + p) * HD + d] : 0.f;
        }
        __syncthreads();

        ull acc[4][2];
        #pragma unroll
        for (int i = 0; i < 4; i++) { acc[i][0] = 0ull; acc[i][1] = 0ull; }

        #pragma unroll 16
        for (int d = 0; d < 64; d++) {
            float4 a4 = *(const float4*)&QsT[d][ty * 4];
            float4 b4 = *(const float4*)&RsT[d][tx * 4];
            ull bp0 = pack2(b4.x, b4.y), bp1 = pack2(b4.z, b4.w);
            float a[4] = {a4.x, a4.y, a4.z, a4.w};
            #pragma unroll
            for (int i = 0; i < 4; i++) {
                ull ap = pack2(a[i], a[i]);
                acc[i][0] = fma2(ap, bp0, acc[i][0]);
                acc[i][1] = fma2(ap, bp1, acc[i][1]);
            }
        }

        #pragma unroll
        for (int i = 0; i < 4; i++) {
            float2 c0 = unpack2(acc[i][0]), c1 = unpack2(acc[i][1]);
            float cv[4] = {c0.x, c0.y, c1.x, c1.y};
            #pragma unroll
            for (int j = 0; j < 4; j++) {
                int p = p0 + tx * 4 + j;
                if (p < NP)
                    orow[(size_t)(ty * 4 + i) * NP + p] = cv[j];
            }
        }
    }
}

// ---------------------------------------------------------------------------
// Banded flash attention with relative-position bias (FFMA2 inner loops).
// TQ=64 queries, TK=32 keys per tile, window |j-i| <= 256.
// grid (SEQ/64, NH, BATCH), 256 threads (16x16).
// ---------------------------------------------------------------------------
__global__ __launch_bounds__(256) void attn_kernel(
    const float* __restrict__ Qp, const float* __restrict__ Kp,
    const float* __restrict__ Vp, float* __restrict__ CTX)
{
    __shared__ float Qt[64][68];   // [d][r]
    __shared__ float Kt[64][34];   // [d][c]
    __shared__ float Vs[32][68];   // [c][d]
    __shared__ float PsT[32][68];  // [c][r]
    __shared__ float red[64][17];

    const int i0 = blockIdx.x * 64;
    const int h = blockIdx.y, b = blockIdx.z;
    const int tid = threadIdx.x, tx = tid & 15, ty = tid >> 4;

    const size_t base = ((size_t)b * SEQ) * DIMM + h * HD;

    for (int idx = tid; idx < 64 * 64; idx += 256) {
        int r = idx >> 6, d = idx & 63;
        Qt[d][r] = Qp[base + (size_t)(i0 + r) * DIMM + d];
    }

    float mrow[4], lrow[4];
    ull Op[4][2];
    #pragma unroll
    for (int i = 0; i < 4; i++) {
        mrow[i] = -1e30f; lrow[i] = 0.f;
        Op[i][0] = 0ull; Op[i][1] = 0ull;
    }

    const float* qrl = g_qrel + (((size_t)b * NH + h) * SEQ) * NP;

    int jstart = i0 - RADIUS; if (jstart < 0) jstart = 0;
    int jend = i0 + 64 + RADIUS; if (jend > SEQ) jend = SEQ;

    __syncthreads();

    for (int j0 = jstart; j0 < jend; j0 += 32) {
        // load K,V tiles
        for (int idx = tid; idx < 32 * 64; idx += 256) {
            int c = idx >> 6, d = idx & 63;
            size_t g = base + (size_t)(j0 + c) * DIMM + d;
            Kt[d][c] = Kp[g];
            Vs[c][d] = Vp[g];
        }
        __syncthreads();

        // S = Q K^T   (rows packed in i-pairs)
        ull sp[2][2];
        sp[0][0] = 0ull; sp[0][1] = 0ull; sp[1][0] = 0ull; sp[1][1] = 0ull;

        #pragma unroll 16
        for (int d = 0; d < 64; d++) {
            float4 a4 = *(const float4*)&Qt[d][ty * 4];
            float2 b2 = *(const float2*)&Kt[d][tx * 2];
            ull a01 = pack2(a4.x, a4.y), a23 = pack2(a4.z, a4.w);
            ull b00 = pack2(b2.x, b2.x), b11 = pack2(b2.y, b2.y);
            sp[0][0] = fma2(a01, b00, sp[0][0]);
            sp[0][1] = fma2(a01, b11, sp[0][1]);
            sp[1][0] = fma2(a23, b00, sp[1][0]);
            sp[1][1] = fma2(a23, b11, sp[1][1]);
        }

        float s[4][2];
        {
            float2 u;
            u = unpack2(sp[0][0]); s[0][0] = u.x; s[1][0] = u.y;
            u = unpack2(sp[0][1]); s[0][1] = u.x; s[1][1] = u.y;
            u = unpack2(sp[1][0]); s[2][0] = u.x; s[3][0] = u.y;
            u = unpack2(sp[1][1]); s[2][1] = u.x; s[3][1] = u.y;
        }

        // rel bias + mask + scale
        #pragma unroll
        for (int i = 0; i < 4; i++) {
            const int gi = i0 + ty * 4 + i;
            #pragma unroll
            for (int j = 0; j < 2; j++) {
                const int gj = j0 + tx * 2 + j;
                const int dl = gj - gi;
                if (dl > RADIUS || dl < -RADIUS) {
                    s[i][j] = -1e30f;
                } else {
                    int p = dl; if (p > RREL) p = RREL; if (p < -RREL) p = -RREL;
                    s[i][j] = (s[i][j] + qrl[(size_t)gi * NP + p + RREL]) * 0.125f;
                }
            }
        }

        // online softmax: row max
        #pragma unroll
        for (int i = 0; i < 4; i++)
            red[ty * 4 + i][tx] = fmaxf(s[i][0], s[i][1]);
        __syncthreads();

        float scl[4], psum[4];
        #pragma unroll
        for (int i = 0; i < 4; i++) {
            float rm = -1e30f;
            #pragma unroll
            for (int t = 0; t < 16; t++) rm = fmaxf(rm, red[ty * 4 + i][t]);
            float mn = fmaxf(mrow[i], rm);
            scl[i] = __expf(mrow[i] - mn);
            mrow[i] = mn;
            float p0 = __expf(s[i][0] - mn);
            float p1 = __expf(s[i][1] - mn);
            s[i][0] = p0; s[i][1] = p1;
            psum[i] = p0 + p1;
        }
        __syncthreads();   // done reading red (max pass)

        #pragma unroll
        for (int i = 0; i < 4; i++) {
            red[ty * 4 + i][tx] = psum[i];
            PsT[tx * 2 + 0][ty * 4 + i] = s[i][0];
            PsT[tx * 2 + 1][ty * 4 + i] = s[i][1];
        }
        __syncthreads();

        #pragma unroll
        for (int i = 0; i < 4; i++) {
            float rs = 0.f;
            #pragma unroll
            for (int t = 0; t < 16; t++) rs += red[ty * 4 + i][t];
            lrow[i] = lrow[i] * scl[i] + rs;
            ull sclp = pack2(scl[i], scl[i]);
            Op[i][0] = mul2(Op[i][0], sclp);
            Op[i][1] = mul2(Op[i][1], sclp);
        }

        // O += P V
        #pragma unroll 8
        for (int c = 0; c < 32; c++) {
            float4 a4 = *(const float4*)&PsT[c][ty * 4];
            float4 b4 = *(const float4*)&Vs[c][tx * 4];
            ull bp0 = pack2(b4.x, b4.y), bp1 = pack2(b4.z, b4.w);
            float a[4] = {a4.x, a4.y, a4.z, a4.w};
            #pragma unroll
            for (int i = 0; i < 4; i++) {
                ull ap = pack2(a[i], a[i]);
                Op[i][0] = fma2(ap, bp0, Op[i][0]);
                Op[i][1] = fma2(ap, bp1, Op[i][1]);
            }
        }
        __syncthreads();   // protect Kt/Vs/PsT/red before next tile
    }

    #pragma unroll
    for (int i = 0; i < 4; i++) {
        float inv = 1.f / lrow[i];
        float2 o0 = unpack2(Op[i][0]), o1 = unpack2(Op[i][1]);
        float4 ov = make_float4(o0.x * inv, o0.y * inv, o1.x * inv, o1.y * inv);
        *(float4*)&CTX[base + (size_t)(i0 + ty * 4 + i) * DIMM + tx * 4] = ov;
    }
}

// ---------------------------------------------------------------------------
// Launch
// ---------------------------------------------------------------------------
extern "C" void kernel_launch(void* const* d_in, const int* in_sizes, int n_in,
                              void* d_out, int out_size)
{
    const float* Q  = (const float*)d_in[0];
    const float* K  = (const float*)d_in[1];
    const float* V  = (const float*)d_in[2];
    const float* Wq = (const float*)d_in[3];
    const float* Wk = (const float*)d_in[4];
    const float* Wv = (const float*)d_in[5];
    const float* Wo = (const float*)d_in[6];
    const float* E  = (const float*)d_in[7];
    float* out = (float*)d_out;

    float *q, *k, *v, *ctx, *wop;
    cudaGetSymbolAddress((void**)&q,   g_q);
    cudaGetSymbolAddress((void**)&k,   g_k);
    cudaGetSymbolAddress((void**)&v,   g_v);
    cudaGetSymbolAddress((void**)&ctx, g_ctx);
    cudaGetSymbolAddress((void**)&wop, g_wop);

    const int M = BATCH * SEQ;            // 4096
    dim3 gemm_grid(DIMM / 128, M / 128);  // (8, 32)

    // projections
    sgemm_nt<<<gemm_grid, 256>>>(Q, Wq, q, M, DIMM, DIMM);
    sgemm_nt<<<gemm_grid, 256>>>(K, Wk, k, M, DIMM, DIMM);
    sgemm_nt<<<gemm_grid, 256>>>(V, Wv, v, M, DIMM, DIMM);

    // permutes
    relT_kernel<<<(NH * NP * HD + 255) / 256, 256>>>(E);
    wop_kernel<<<(DIMM * DIMM) / 256, 256>>>(Wo);

    // relative-position logits
    qrel_kernel<<<dim3(SEQ / 64, NH, BATCH), 256>>>(q);

    // banded attention
    attn_kernel<<<dim3(SEQ / 64, NH, BATCH), 256>>>(q, k, v, ctx);

    // output projection (with permuted Wo)
    sgemm_nt<<<gemm_grid, 256>>>(ctx, wop, out, M, DIMM, DIMM);
}

// round 4
// speedup vs baseline: 1.5737x; 1.5397x over previous
#include <cuda_runtime.h>
#include <cuda_bf16.h>
#include <cstdint>

// Problem constants
#define BATCH 2
#define SEQ   2048
#define DIMM  1024
#define NH    16
#define HD    64
#define NP    257
#define RREL  128
#define RADIUS 256
#define NELEM (BATCH * SEQ * DIMM)   // 4194304

typedef unsigned long long ull;

// ---------------------------------------------------------------------------
// f32x2 helpers (attention)
// ---------------------------------------------------------------------------
__device__ __forceinline__ ull pack2(float x, float y) {
    ull r; asm("mov.b64 %0, {%1, %2};" : "=l"(r) : "f"(x), "f"(y)); return r;
}
__device__ __forceinline__ float2 unpack2(ull v) {
    float2 r; asm("mov.b64 {%0, %1}, %2;" : "=f"(r.x), "=f"(r.y) : "l"(v)); return r;
}
__device__ __forceinline__ ull fma2(ull a, ull b, ull c) {
    ull d; asm("fma.rn.f32x2 %0, %1, %2, %3;" : "=l"(d) : "l"(a), "l"(b), "l"(c)); return d;
}
__device__ __forceinline__ ull mul2(ull a, ull b) {
    ull d; asm("mul.rn.f32x2 %0, %1, %2;" : "=l"(d) : "l"(a), "l"(b)); return d;
}

// ---------------------------------------------------------------------------
// Tensor-core (mma.sync, arch-portable) helpers
// ---------------------------------------------------------------------------
__device__ __forceinline__ uint32_t smem_u32(const void* p) {
    uint32_t a;
    asm("{ .reg .u64 t; cvta.to.shared.u64 t, %1; cvt.u32.u64 %0, t; }" : "=r"(a) : "l"(p));
    return a;
}

#define LDSM4(r, addr) \
    asm volatile("ldmatrix.sync.aligned.m8n8.x4.shared.b16 {%0,%1,%2,%3}, [%4];" \
        : "=r"((r)[0]), "=r"((r)[1]), "=r"((r)[2]), "=r"((r)[3]) : "r"(addr))

#define MMA16816(d, a, b0, b1) \
    asm volatile("mma.sync.aligned.m16n8k16.row.col.f32.bf16.bf16.f32 " \
        "{%0,%1,%2,%3}, {%4,%5,%6,%7}, {%8,%9}, {%0,%1,%2,%3};" \
        : "+f"((d)[0]), "+f"((d)[1]), "+f"((d)[2]), "+f"((d)[3]) \
        : "r"((a)[0]), "r"((a)[1]), "r"((a)[2]), "r"((a)[3]), "r"(b0), "r"(b1))

#define CP_ASYNC16(sa, ga) \
    asm volatile("cp.async.cg.shared.global [%0], [%1], 16;" :: "r"(sa), "l"(ga))
#define CP_COMMIT() asm volatile("cp.async.commit_group;" ::: "memory")
#define CP_WAIT(n)  asm volatile("cp.async.wait_group %0;" :: "n"(n) : "memory")

// ---------------------------------------------------------------------------
// Device scratch
// ---------------------------------------------------------------------------
__device__ float g_q[NELEM];
__device__ float g_k[NELEM];
__device__ float g_v[NELEM];
__device__ float g_relT[NH * NP * HD];
__device__ float g_qrel[(size_t)BATCH * NH * SEQ * NP];

__device__ __nv_bfloat16 g_qin_h[NELEM], g_qin_l[NELEM];
__device__ __nv_bfloat16 g_kin_h[NELEM], g_kin_l[NELEM];
__device__ __nv_bfloat16 g_vin_h[NELEM], g_vin_l[NELEM];
__device__ __nv_bfloat16 g_ctx_h[NELEM], g_ctx_l[NELEM];
__device__ __nv_bfloat16 g_wq_h[DIMM * DIMM], g_wq_l[DIMM * DIMM];
__device__ __nv_bfloat16 g_wk_h[DIMM * DIMM], g_wk_l[DIMM * DIMM];
__device__ __nv_bfloat16 g_wv_h[DIMM * DIMM], g_wv_l[DIMM * DIMM];
__device__ __nv_bfloat16 g_wo_h[DIMM * DIMM], g_wo_l[DIMM * DIMM];

// ---------------------------------------------------------------------------
// fp32 -> bf16 hi/lo split
// ---------------------------------------------------------------------------
__global__ void split_kernel(const float* __restrict__ in,
                             __nv_bfloat16* __restrict__ hi,
                             __nv_bfloat16* __restrict__ lo, int n)
{
    int i = blockIdx.x * 256 + threadIdx.x;
    if (i < n) {
        float x = in[i];
        __nv_bfloat16 h = __float2bfloat16(x);
        hi[i] = h;
        lo[i] = __float2bfloat16(x - __bfloat162float(h));
    }
}

// Wo permute + split: WoP[n,k] = Wo[n, (k%64)*16 + k/64]
__global__ void wop_split_kernel(const float* __restrict__ Wo)
{
    int idx = blockIdx.x * 256 + threadIdx.x;
    if (idx < DIMM * DIMM) {
        int k = idx & 1023, n = idx >> 10;
        float x = Wo[(size_t)n * DIMM + (k & 63) * NH + (k >> 6)];
        __nv_bfloat16 h = __float2bfloat16(x);
        g_wo_h[idx] = h;
        g_wo_l[idx] = __float2bfloat16(x - __bfloat162float(h));
    }
}

// ---------------------------------------------------------------------------
// Warp-MMA split GEMM: C[M,N] = A[M,K] @ W[N,K]^T, fp32-equivalent via
// Ah*Wh + Ah*Wl + Al*Wh on mma.sync m16n8k16 bf16.
// CTA tile 128x128, 8 warps (4x2, each 32x64), BK=32, cp.async double buffer.
// Smem rows padded to 80B -> conflict-free ldmatrix.
// ---------------------------------------------------------------------------
#define BKB 32
#define NSTG (DIMM / BKB)            // 32
#define ROWB 80                      // padded row bytes (32 bf16 + 8 pad)
#define TILE_B (128 * ROWB)          // 10240
#define STG_B (4 * TILE_B)           // 40960
#define GEMM_SMEM (2 * STG_B)        // 81920

__device__ __forceinline__ void gemm_load_stage(
    uint32_t sbase, int s, int m0, int n0,
    const __nv_bfloat16* __restrict__ Ah, const __nv_bfloat16* __restrict__ Al,
    const __nv_bfloat16* __restrict__ Bh, const __nv_bfloat16* __restrict__ Bl,
    int K, int tid)
{
    const int k0 = s * BKB;
    const uint32_t dst = sbase + (uint32_t)(s & 1) * STG_B;
    const __nv_bfloat16* srcs[4] = {Ah, Al, Bh, Bl};
    #pragma unroll
    for (int t = 0; t < 4; t++) {
        const __nv_bfloat16* src = srcs[t];
        const int r0 = (t < 2) ? m0 : n0;
        #pragma unroll
        for (int rep = 0; rep < 2; rep++) {
            const int c = tid + rep * 256;       // 0..511
            const int row = c >> 2, ch = c & 3;
            const uint32_t sa = dst + (uint32_t)t * TILE_B + row * ROWB + ch * 16;
            const void* ga = src + (size_t)(r0 + row) * K + k0 + ch * 8;
            CP_ASYNC16(sa, ga);
        }
    }
    CP_COMMIT();
}

__global__ __launch_bounds__(256, 1) void gemm_hmma(
    const __nv_bfloat16* __restrict__ Ah, const __nv_bfloat16* __restrict__ Al,
    const __nv_bfloat16* __restrict__ Bh, const __nv_bfloat16* __restrict__ Bl,
    float* __restrict__ C, int M, int N, int K)
{
    extern __shared__ __align__(128) char sm[];
    const uint32_t sbase = smem_u32(sm);

    const int tid = threadIdx.x, lane = tid & 31, wid = tid >> 5;
    const int wm = wid >> 1, wn = wid & 1;       // warp grid 4x2
    const int m0 = blockIdx.y * 128, n0 = blockIdx.x * 128;

    float acc[2][8][4];
    #pragma unroll
    for (int i = 0; i < 2; i++)
        #pragma unroll
        for (int j = 0; j < 8; j++)
            #pragma unroll
            for (int r = 0; r < 4; r++) acc[i][j][r] = 0.f;

    gemm_load_stage(sbase, 0, m0, n0, Ah, Al, Bh, Bl, K, tid);

    // per-lane base offsets within a stage
    const uint32_t a_lane = (uint32_t)((wm * 32 + (lane & 15)) * ROWB + (lane >> 4) * 16);
    const uint32_t b_lane = (uint32_t)((wn * 64 + (lane & 15)) * ROWB + (lane >> 4) * 16)
                          + 2u * TILE_B;

    for (int s = 0; s < NSTG; s++) {
        if (s + 1 < NSTG) {
            gemm_load_stage(sbase, s + 1, m0, n0, Ah, Al, Bh, Bl, K, tid);
            CP_WAIT(1);
        } else {
            CP_WAIT(0);
        }
        __syncthreads();

        const uint32_t st = sbase + (uint32_t)(s & 1) * STG_B;

        #pragma unroll
        for (int kk = 0; kk < 2; kk++) {         // two k16 sub-steps
            uint32_t ah[2][4], al[2][4];
            #pragma unroll
            for (int mi = 0; mi < 2; mi++) {
                const uint32_t aaddr = st + a_lane + (uint32_t)(mi * 16 * ROWB) + kk * 32;
                LDSM4(ah[mi], aaddr);
                LDSM4(al[mi], aaddr + TILE_B);
            }
            #pragma unroll
            for (int g = 0; g < 4; g++) {        // four n16 groups
                const uint32_t baddr = st + b_lane + (uint32_t)(g * 16 * ROWB) + kk * 32;
                uint32_t bh[4], bl[4];
                LDSM4(bh, baddr);
                LDSM4(bl, baddr + TILE_B);
                #pragma unroll
                for (int mi = 0; mi < 2; mi++) {
                    MMA16816(acc[mi][2 * g],     ah[mi], bh[0], bh[2]);
                    MMA16816(acc[mi][2 * g],     ah[mi], bl[0], bl[2]);
                    MMA16816(acc[mi][2 * g],     al[mi], bh[0], bh[2]);
                    MMA16816(acc[mi][2 * g + 1], ah[mi], bh[1], bh[3]);
                    MMA16816(acc[mi][2 * g + 1], ah[mi], bl[1], bl[3]);
                    MMA16816(acc[mi][2 * g + 1], al[mi], bh[1], bh[3]);
                }
            }
        }
        __syncthreads();
    }

    #pragma unroll
    for (int mi = 0; mi < 2; mi++) {
        const int row = m0 + wm * 32 + mi * 16 + (lane >> 2);
        #pragma unroll
        for (int nj = 0; nj < 8; nj++) {
            const int col = n0 + wn * 64 + nj * 8 + (lane & 3) * 2;
            *(float2*)&C[(size_t)row * N + col] =
                make_float2(acc[mi][nj][0], acc[mi][nj][1]);
            *(float2*)&C[(size_t)(row + 8) * N + col] =
                make_float2(acc[mi][nj][2], acc[mi][nj][3]);
        }
    }
}

// ---------------------------------------------------------------------------
// relT[h,p,d] = E[p, d*16 + h]
// ---------------------------------------------------------------------------
__global__ void relT_kernel(const float* __restrict__ E)
{
    int idx = blockIdx.x * 256 + threadIdx.x;
    if (idx < NH * NP * HD) {
        int d = idx & 63;
        int p = (idx >> 6) % NP;
        int h = idx / (NP * HD);
        g_relT[idx] = E[(size_t)p * DIMM + d * NH + h];
    }
}

// ---------------------------------------------------------------------------
// qrel[b,h,s,p] = sum_d q[b,h,s,d] * relT[h,p,d]
// ---------------------------------------------------------------------------
__global__ __launch_bounds__(256) void qrel_kernel(const float* __restrict__ Qp)
{
    __shared__ float QsT[64][68];
    __shared__ float RsT[64][68];

    const int i0 = blockIdx.x * 64;
    const int h = blockIdx.y, b = blockIdx.z;
    const int tid = threadIdx.x, tx = tid & 15, ty = tid >> 4;

    const size_t qbase = ((size_t)b * SEQ) * DIMM + h * HD;
    for (int idx = tid; idx < 64 * 64; idx += 256) {
        int r = idx >> 6, d = idx & 63;
        QsT[d][r] = Qp[qbase + (size_t)(i0 + r) * DIMM + d];
    }

    float* orow = g_qrel + (((size_t)b * NH + h) * SEQ + i0) * NP;

    for (int p0 = 0; p0 < NP; p0 += 64) {
        __syncthreads();
        for (int idx = tid; idx < 64 * 64; idx += 256) {
            int pp = idx >> 6, d = idx & 63;
            int p = p0 + pp;
            RsT[d][pp] = (p < NP) ? g_relT[((size_t)h * NP + p) * HD + d] : 0.f;
        }
        __syncthreads();

        ull acc[4][2];
        #pragma unroll
        for (int i = 0; i < 4; i++) { acc[i][0] = 0ull; acc[i][1] = 0ull; }

        #pragma unroll 16
        for (int d = 0; d < 64; d++) {
            float4 a4 = *(const float4*)&QsT[d][ty * 4];
            float4 b4 = *(const float4*)&RsT[d][tx * 4];
            ull bp0 = pack2(b4.x, b4.y), bp1 = pack2(b4.z, b4.w);
            float a[4] = {a4.x, a4.y, a4.z, a4.w};
            #pragma unroll
            for (int i = 0; i < 4; i++) {
                ull ap = pack2(a[i], a[i]);
                acc[i][0] = fma2(ap, bp0, acc[i][0]);
                acc[i][1] = fma2(ap, bp1, acc[i][1]);
            }
        }

        #pragma unroll
        for (int i = 0; i < 4; i++) {
            float2 c0 = unpack2(acc[i][0]), c1 = unpack2(acc[i][1]);
            float cv[4] = {c0.x, c0.y, c1.x, c1.y};
            #pragma unroll
            for (int j = 0; j < 4; j++) {
                int p = p0 + tx * 4 + j;
                if (p < NP)
                    orow[(size_t)(ty * 4 + i) * NP + p] = cv[j];
            }
        }
    }
}

// ---------------------------------------------------------------------------
// Banded flash attention with relative-position bias.
// Writes ctx directly as bf16 hi/lo splits (feeds the Wo GEMM).
// ---------------------------------------------------------------------------
__global__ __launch_bounds__(256) void attn_kernel(
    const float* __restrict__ Qp, const float* __restrict__ Kp,
    const float* __restrict__ Vp,
    __nv_bfloat16* __restrict__ CXH, __nv_bfloat16* __restrict__ CXL)
{
    __shared__ float Qt[64][68];
    __shared__ float Kt[64][34];
    __shared__ float Vs[32][68];
    __shared__ float PsT[32][68];
    __shared__ float red[64][17];

    const int i0 = blockIdx.x * 64;
    const int h = blockIdx.y, b = blockIdx.z;
    const int tid = threadIdx.x, tx = tid & 15, ty = tid >> 4;

    const size_t base = ((size_t)b * SEQ) * DIMM + h * HD;

    for (int idx = tid; idx < 64 * 64; idx += 256) {
        int r = idx >> 6, d = idx & 63;
        Qt[d][r] = Qp[base + (size_t)(i0 + r) * DIMM + d];
    }

    float mrow[4], lrow[4];
    ull Op[4][2];
    #pragma unroll
    for (int i = 0; i < 4; i++) {
        mrow[i] = -1e30f; lrow[i] = 0.f;
        Op[i][0] = 0ull; Op[i][1] = 0ull;
    }

    const float* qrl = g_qrel + (((size_t)b * NH + h) * SEQ) * NP;

    int jstart = i0 - RADIUS; if (jstart < 0) jstart = 0;
    int jend = i0 + 64 + RADIUS; if (jend > SEQ) jend = SEQ;

    __syncthreads();

    for (int j0 = jstart; j0 < jend; j0 += 32) {
        for (int idx = tid; idx < 32 * 64; idx += 256) {
            int c = idx >> 6, d = idx & 63;
            size_t g = base + (size_t)(j0 + c) * DIMM + d;
            Kt[d][c] = Kp[g];
            Vs[c][d] = Vp[g];
        }
        __syncthreads();

        ull sp[2][2];
        sp[0][0] = 0ull; sp[0][1] = 0ull; sp[1][0] = 0ull; sp[1][1] = 0ull;

        #pragma unroll 16
        for (int d = 0; d < 64; d++) {
            float4 a4 = *(const float4*)&Qt[d][ty * 4];
            float2 b2 = *(const float2*)&Kt[d][tx * 2];
            ull a01 = pack2(a4.x, a4.y), a23 = pack2(a4.z, a4.w);
            ull b00 = pack2(b2.x, b2.x), b11 = pack2(b2.y, b2.y);
            sp[0][0] = fma2(a01, b00, sp[0][0]);
            sp[0][1] = fma2(a01, b11, sp[0][1]);
            sp[1][0] = fma2(a23, b00, sp[1][0]);
            sp[1][1] = fma2(a23, b11, sp[1][1]);
        }

        float s[4][2];
        {
            float2 u;
            u = unpack2(sp[0][0]); s[0][0] = u.x; s[1][0] = u.y;
            u = unpack2(sp[0][1]); s[0][1] = u.x; s[1][1] = u.y;
            u = unpack2(sp[1][0]); s[2][0] = u.x; s[3][0] = u.y;
            u = unpack2(sp[1][1]); s[2][1] = u.x; s[3][1] = u.y;
        }

        #pragma unroll
        for (int i = 0; i < 4; i++) {
            const int gi = i0 + ty * 4 + i;
            #pragma unroll
            for (int j = 0; j < 2; j++) {
                const int gj = j0 + tx * 2 + j;
                const int dl = gj - gi;
                if (dl > RADIUS || dl < -RADIUS) {
                    s[i][j] = -1e30f;
                } else {
                    int p = dl; if (p > RREL) p = RREL; if (p < -RREL) p = -RREL;
                    s[i][j] = (s[i][j] + qrl[(size_t)gi * NP + p + RREL]) * 0.125f;
                }
            }
        }

        #pragma unroll
        for (int i = 0; i < 4; i++)
            red[ty * 4 + i][tx] = fmaxf(s[i][0], s[i][1]);
        __syncthreads();

        float scl[4], psum[4];
        #pragma unroll
        for (int i = 0; i < 4; i++) {
            float rm = -1e30f;
            #pragma unroll
            for (int t = 0; t < 16; t++) rm = fmaxf(rm, red[ty * 4 + i][t]);
            float mn = fmaxf(mrow[i], rm);
            scl[i] = __expf(mrow[i] - mn);
            mrow[i] = mn;
            float p0 = __expf(s[i][0] - mn);
            float p1 = __expf(s[i][1] - mn);
            s[i][0] = p0; s[i][1] = p1;
            psum[i] = p0 + p1;
        }
        __syncthreads();

        #pragma unroll
        for (int i = 0; i < 4; i++) {
            red[ty * 4 + i][tx] = psum[i];
            PsT[tx * 2 + 0][ty * 4 + i] = s[i][0];
            PsT[tx * 2 + 1][ty * 4 + i] = s[i][1];
        }
        __syncthreads();

        #pragma unroll
        for (int i = 0; i < 4; i++) {
            float rs = 0.f;
            #pragma unroll
            for (int t = 0; t < 16; t++) rs += red[ty * 4 + i][t];
            lrow[i] = lrow[i] * scl[i] + rs;
            ull sclp = pack2(scl[i], scl[i]);
            Op[i][0] = mul2(Op[i][0], sclp);
            Op[i][1] = mul2(Op[i][1], sclp);
        }

        #pragma unroll 8
        for (int c = 0; c < 32; c++) {
            float4 a4 = *(const float4*)&PsT[c][ty * 4];
            float4 b4 = *(const float4*)&Vs[c][tx * 4];
            ull bp0 = pack2(b4.x, b4.y), bp1 = pack2(b4.z, b4.w);
            float a[4] = {a4.x, a4.y, a4.z, a4.w};
            #pragma unroll
            for (int i = 0; i < 4; i++) {
                ull ap = pack2(a[i], a[i]);
                Op[i][0] = fma2(ap, bp0, Op[i][0]);
                Op[i][1] = fma2(ap, bp1, Op[i][1]);
            }
        }
        __syncthreads();
    }

    #pragma unroll
    for (int i = 0; i < 4; i++) {
        float inv = 1.f / lrow[i];
        float2 o0 = unpack2(Op[i][0]), o1 = unpack2(Op[i][1]);
        float o[4] = {o0.x * inv, o0.y * inv, o1.x * inv, o1.y * inv};
        __nv_bfloat16 hh[4], ll[4];
        #pragma unroll
        for (int j = 0; j < 4; j++) {
            hh[j] = __float2bfloat16(o[j]);
            ll[j] = __float2bfloat16(o[j] - __bfloat162float(hh[j]));
        }
        const size_t off = base + (size_t)(i0 + ty * 4 + i) * DIMM + tx * 4;
        *(uint2*)&CXH[off] = *(const uint2*)hh;
        *(uint2*)&CXL[off] = *(const uint2*)ll;
    }
}

// ---------------------------------------------------------------------------
// Launch
// ---------------------------------------------------------------------------
extern "C" void kernel_launch(void* const* d_in, const int* in_sizes, int n_in,
                              void* d_out, int out_size)
{
    const float* Q  = (const float*)d_in[0];
    const float* K  = (const float*)d_in[1];
    const float* V  = (const float*)d_in[2];
    const float* Wq = (const float*)d_in[3];
    const float* Wk = (const float*)d_in[4];
    const float* Wv = (const float*)d_in[5];
    const float* Wo = (const float*)d_in[6];
    const float* E  = (const float*)d_in[7];
    float* out = (float*)d_out;

    float *q, *k, *v;
    cudaGetSymbolAddress((void**)&q, g_q);
    cudaGetSymbolAddress((void**)&k, g_k);
    cudaGetSymbolAddress((void**)&v, g_v);

    __nv_bfloat16 *qih, *qil, *kih, *kil, *vih, *vil, *cxh, *cxl;
    __nv_bfloat16 *wqh, *wql, *wkh, *wkl, *wvh, *wvl, *woh, *wol;
    cudaGetSymbolAddress((void**)&qih, g_qin_h); cudaGetSymbolAddress((void**)&qil, g_qin_l);
    cudaGetSymbolAddress((void**)&kih, g_kin_h); cudaGetSymbolAddress((void**)&kil, g_kin_l);
    cudaGetSymbolAddress((void**)&vih, g_vin_h); cudaGetSymbolAddress((void**)&vil, g_vin_l);
    cudaGetSymbolAddress((void**)&cxh, g_ctx_h); cudaGetSymbolAddress((void**)&cxl, g_ctx_l);
    cudaGetSymbolAddress((void**)&wqh, g_wq_h);  cudaGetSymbolAddress((void**)&wql, g_wq_l);
    cudaGetSymbolAddress((void**)&wkh, g_wk_h);  cudaGetSymbolAddress((void**)&wkl, g_wk_l);
    cudaGetSymbolAddress((void**)&wvh, g_wv_h);  cudaGetSymbolAddress((void**)&wvl, g_wv_l);
    cudaGetSymbolAddress((void**)&woh, g_wo_h);  cudaGetSymbolAddress((void**)&wol, g_wo_l);

    static bool attr_set = false;
    if (!attr_set) {
        cudaFuncSetAttribute(gemm_hmma, cudaFuncAttributeMaxDynamicSharedMemorySize, GEMM_SMEM);
        attr_set = true;
    }

    const int M = BATCH * SEQ;             // 4096
    dim3 tc_grid(DIMM / 128, M / 128);     // (8, 32)

    // input/weight splits
    split_kernel<<<NELEM / 256, 256>>>(Q, qih, qil, NELEM);
    split_kernel<<<NELEM / 256, 256>>>(K, kih, kil, NELEM);
    split_kernel<<<NELEM / 256, 256>>>(V, vih, vil, NELEM);
    split_kernel<<<(DIMM * DIMM) / 256, 256>>>(Wq, wqh, wql, DIMM * DIMM);
    split_kernel<<<(DIMM * DIMM) / 256, 256>>>(Wk, wkh, wkl, DIMM * DIMM);
    split_kernel<<<(DIMM * DIMM) / 256, 256>>>(Wv, wvh, wvl, DIMM * DIMM);
    wop_split_kernel<<<(DIMM * DIMM) / 256, 256>>>(Wo);
    relT_kernel<<<(NH * NP * HD + 255) / 256, 256>>>(E);

    // projections on tensor cores (legacy HMMA path)
    gemm_hmma<<<tc_grid, 256, GEMM_SMEM>>>(qih, qil, wqh, wql, q, M, DIMM, DIMM);
    gemm_hmma<<<tc_grid, 256, GEMM_SMEM>>>(kih, kil, wkh, wkl, k, M, DIMM, DIMM);
    gemm_hmma<<<tc_grid, 256, GEMM_SMEM>>>(vih, vil, wvh, wvl, v, M, DIMM, DIMM);

    // relative-position logits + banded attention (ctx written as bf16 hi/lo)
    qrel_kernel<<<dim3(SEQ / 64, NH, BATCH), 256>>>(q);
    attn_kernel<<<dim3(SEQ / 64, NH, BATCH), 256>>>(q, k, v, cxh, cxl);

    // output projection
    gemm_hmma<<<tc_grid, 256, GEMM_SMEM>>>(cxh, cxl, woh, wol, out, M, DIMM, DIMM);
}

// round 5
// speedup vs baseline: 1.9931x; 1.2666x over previous
#include <cuda_runtime.h>
#include <cuda_bf16.h>
#include <cstdint>

// Problem constants
#define BATCH 2
#define SEQ   2048
#define DIMM  1024
#define NH    16
#define HD    64
#define NP    257
#define RREL  128
#define RADIUS 256
#define NELEM (BATCH * SEQ * DIMM)   // 4194304

typedef unsigned long long ull;

// ---------------------------------------------------------------------------
// f32x2 helpers (qrel kernel)
// ---------------------------------------------------------------------------
__device__ __forceinline__ ull pack2(float x, float y) {
    ull r; asm("mov.b64 %0, {%1, %2};" : "=l"(r) : "f"(x), "f"(y)); return r;
}
__device__ __forceinline__ float2 unpack2(ull v) {
    float2 r; asm("mov.b64 {%0, %1}, %2;" : "=f"(r.x), "=f"(r.y) : "l"(v)); return r;
}
__device__ __forceinline__ ull fma2(ull a, ull b, ull c) {
    ull d; asm("fma.rn.f32x2 %0, %1, %2, %3;" : "=l"(d) : "l"(a), "l"(b), "l"(c)); return d;
}

// ---------------------------------------------------------------------------
// Tensor-core (mma.sync, arch-portable) helpers
// ---------------------------------------------------------------------------
__device__ __forceinline__ uint32_t smem_u32(const void* p) {
    uint32_t a;
    asm("{ .reg .u64 t; cvta.to.shared.u64 t, %1; cvt.u32.u64 %0, t; }" : "=r"(a) : "l"(p));
    return a;
}

#define LDSM4(r, addr) \
    asm volatile("ldmatrix.sync.aligned.m8n8.x4.shared.b16 {%0,%1,%2,%3}, [%4];" \
        : "=r"((r)[0]), "=r"((r)[1]), "=r"((r)[2]), "=r"((r)[3]) : "r"(addr))

#define LDSM4T(r, addr) \
    asm volatile("ldmatrix.sync.aligned.m8n8.x4.trans.shared.b16 {%0,%1,%2,%3}, [%4];" \
        : "=r"((r)[0]), "=r"((r)[1]), "=r"((r)[2]), "=r"((r)[3]) : "r"(addr))

#define MMA16816(d, a, b0, b1) \
    asm volatile("mma.sync.aligned.m16n8k16.row.col.f32.bf16.bf16.f32 " \
        "{%0,%1,%2,%3}, {%4,%5,%6,%7}, {%8,%9}, {%0,%1,%2,%3};" \
        : "+f"((d)[0]), "+f"((d)[1]), "+f"((d)[2]), "+f"((d)[3]) \
        : "r"((a)[0]), "r"((a)[1]), "r"((a)[2]), "r"((a)[3]), "r"(b0), "r"(b1))

#define CP_ASYNC16(sa, ga) \
    asm volatile("cp.async.cg.shared.global [%0], [%1], 16;" :: "r"(sa), "l"(ga))
#define CP_COMMIT() asm volatile("cp.async.commit_group;" ::: "memory")
#define CP_WAIT(n)  asm volatile("cp.async.wait_group %0;" :: "n"(n) : "memory")

// ---------------------------------------------------------------------------
// Device scratch
// ---------------------------------------------------------------------------
__device__ float g_q[NELEM];                              // projected q fp32 (for qrel)
__device__ float g_relT[NH * NP * HD];
__device__ float g_qrel[(size_t)BATCH * NH * SEQ * NP];

__device__ __nv_bfloat16 g_qin_h[NELEM], g_qin_l[NELEM];
__device__ __nv_bfloat16 g_kin_h[NELEM], g_kin_l[NELEM];
__device__ __nv_bfloat16 g_vin_h[NELEM], g_vin_l[NELEM];
__device__ __nv_bfloat16 g_qp_h[NELEM],  g_qp_l[NELEM];   // projected splits
__device__ __nv_bfloat16 g_kp_h[NELEM],  g_kp_l[NELEM];
__device__ __nv_bfloat16 g_vp_h[NELEM],  g_vp_l[NELEM];
__device__ __nv_bfloat16 g_ctx_h[NELEM], g_ctx_l[NELEM];
__device__ __nv_bfloat16 g_wq_h[DIMM * DIMM], g_wq_l[DIMM * DIMM];
__device__ __nv_bfloat16 g_wk_h[DIMM * DIMM], g_wk_l[DIMM * DIMM];
__device__ __nv_bfloat16 g_wv_h[DIMM * DIMM], g_wv_l[DIMM * DIMM];
__device__ __nv_bfloat16 g_wo_h[DIMM * DIMM], g_wo_l[DIMM * DIMM];

// ---------------------------------------------------------------------------
// fp32 -> bf16 hi/lo split
// ---------------------------------------------------------------------------
__global__ void split_kernel(const float* __restrict__ in,
                             __nv_bfloat16* __restrict__ hi,
                             __nv_bfloat16* __restrict__ lo, int n)
{
    int i = blockIdx.x * 256 + threadIdx.x;
    if (i < n) {
        float x = in[i];
        __nv_bfloat16 h = __float2bfloat16(x);
        hi[i] = h;
        lo[i] = __float2bfloat16(x - __bfloat162float(h));
    }
}

__global__ void wop_split_kernel(const float* __restrict__ Wo)
{
    int idx = blockIdx.x * 256 + threadIdx.x;
    if (idx < DIMM * DIMM) {
        int k = idx & 1023, n = idx >> 10;
        float x = Wo[(size_t)n * DIMM + (k & 63) * NH + (k >> 6)];
        __nv_bfloat16 h = __float2bfloat16(x);
        g_wo_h[idx] = h;
        g_wo_l[idx] = __float2bfloat16(x - __bfloat162float(h));
    }
}

// ---------------------------------------------------------------------------
// Warp-MMA split GEMM, epilogue writes optional fp32 C and bf16 hi/lo splits.
// ---------------------------------------------------------------------------
#define BKB 32
#define NSTG (DIMM / BKB)            // 32
#define ROWB 80
#define TILE_B (128 * ROWB)
#define STG_B (4 * TILE_B)
#define GEMM_SMEM (2 * STG_B)        // 81920

__device__ __forceinline__ void gemm_load_stage(
    uint32_t sbase, int s, int m0, int n0,
    const __nv_bfloat16* __restrict__ Ah, const __nv_bfloat16* __restrict__ Al,
    const __nv_bfloat16* __restrict__ Bh, const __nv_bfloat16* __restrict__ Bl,
    int K, int tid)
{
    const int k0 = s * BKB;
    const uint32_t dst = sbase + (uint32_t)(s & 1) * STG_B;
    const __nv_bfloat16* srcs[4] = {Ah, Al, Bh, Bl};
    #pragma unroll
    for (int t = 0; t < 4; t++) {
        const __nv_bfloat16* src = srcs[t];
        const int r0 = (t < 2) ? m0 : n0;
        #pragma unroll
        for (int rep = 0; rep < 2; rep++) {
            const int c = tid + rep * 256;
            const int row = c >> 2, ch = c & 3;
            const uint32_t sa = dst + (uint32_t)t * TILE_B + row * ROWB + ch * 16;
            const void* ga = src + (size_t)(r0 + row) * K + k0 + ch * 8;
            CP_ASYNC16(sa, ga);
        }
    }
    CP_COMMIT();
}

__global__ __launch_bounds__(256, 1) void gemm_hmma(
    const __nv_bfloat16* __restrict__ Ah, const __nv_bfloat16* __restrict__ Al,
    const __nv_bfloat16* __restrict__ Bh, const __nv_bfloat16* __restrict__ Bl,
    float* __restrict__ C,
    __nv_bfloat16* __restrict__ CH, __nv_bfloat16* __restrict__ CL,
    int M, int N, int K)
{
    extern __shared__ __align__(128) char sm[];
    const uint32_t sbase = smem_u32(sm);

    const int tid = threadIdx.x, lane = tid & 31, wid = tid >> 5;
    const int wm = wid >> 1, wn = wid & 1;
    const int m0 = blockIdx.y * 128, n0 = blockIdx.x * 128;

    float acc[2][8][4];
    #pragma unroll
    for (int i = 0; i < 2; i++)
        #pragma unroll
        for (int j = 0; j < 8; j++)
            #pragma unroll
            for (int r = 0; r < 4; r++) acc[i][j][r] = 0.f;

    gemm_load_stage(sbase, 0, m0, n0, Ah, Al, Bh, Bl, K, tid);

    const uint32_t a_lane = (uint32_t)((wm * 32 + (lane & 15)) * ROWB + (lane >> 4) * 16);
    const uint32_t b_lane = (uint32_t)((wn * 64 + (lane & 15)) * ROWB + (lane >> 4) * 16)
                          + 2u * TILE_B;

    for (int s = 0; s < NSTG; s++) {
        if (s + 1 < NSTG) {
            gemm_load_stage(sbase, s + 1, m0, n0, Ah, Al, Bh, Bl, K, tid);
            CP_WAIT(1);
        } else {
            CP_WAIT(0);
        }
        __syncthreads();

        const uint32_t st = sbase + (uint32_t)(s & 1) * STG_B;

        #pragma unroll
        for (int kk = 0; kk < 2; kk++) {
            uint32_t ah[2][4], al[2][4];
            #pragma unroll
            for (int mi = 0; mi < 2; mi++) {
                const uint32_t aaddr = st + a_lane + (uint32_t)(mi * 16 * ROWB) + kk * 32;
                LDSM4(ah[mi], aaddr);
                LDSM4(al[mi], aaddr + TILE_B);
            }
            #pragma unroll
            for (int g = 0; g < 4; g++) {
                const uint32_t baddr = st + b_lane + (uint32_t)(g * 16 * ROWB) + kk * 32;
                uint32_t bh[4], bl[4];
                LDSM4(bh, baddr);
                LDSM4(bl, baddr + TILE_B);
                #pragma unroll
                for (int mi = 0; mi < 2; mi++) {
                    MMA16816(acc[mi][2 * g],     ah[mi], bh[0], bh[2]);
                    MMA16816(acc[mi][2 * g],     ah[mi], bl[0], bl[2]);
                    MMA16816(acc[mi][2 * g],     al[mi], bh[0], bh[2]);
                    MMA16816(acc[mi][2 * g + 1], ah[mi], bh[1], bh[3]);
                    MMA16816(acc[mi][2 * g + 1], ah[mi], bl[1], bl[3]);
                    MMA16816(acc[mi][2 * g + 1], al[mi], bh[1], bh[3]);
                }
            }
        }
        __syncthreads();
    }

    #pragma unroll
    for (int mi = 0; mi < 2; mi++) {
        const int row = m0 + wm * 32 + mi * 16 + (lane >> 2);
        #pragma unroll
        for (int nj = 0; nj < 8; nj++) {
            const int col = n0 + wn * 64 + nj * 8 + (lane & 3) * 2;
            const float* a = acc[mi][nj];
            if (C) {
                *(float2*)&C[(size_t)row * N + col] = make_float2(a[0], a[1]);
                *(float2*)&C[(size_t)(row + 8) * N + col] = make_float2(a[2], a[3]);
            }
            if (CH) {
                #pragma unroll
                for (int hrow = 0; hrow < 2; hrow++) {
                    float x0 = a[hrow * 2], x1 = a[hrow * 2 + 1];
                    __nv_bfloat162 h2 = __float22bfloat162_rn(make_float2(x0, x1));
                    float2 back = __bfloat1622float2(h2);
                    __nv_bfloat162 l2 = __float22bfloat162_rn(
                        make_float2(x0 - back.x, x1 - back.y));
                    const size_t off = (size_t)(row + hrow * 8) * N + col;
                    *(__nv_bfloat162*)&CH[off] = h2;
                    *(__nv_bfloat162*)&CL[off] = l2;
                }
            }
        }
    }
}

// ---------------------------------------------------------------------------
// relT[h,p,d] = E[p, d*16 + h]
// ---------------------------------------------------------------------------
__global__ void relT_kernel(const float* __restrict__ E)
{
    int idx = blockIdx.x * 256 + threadIdx.x;
    if (idx < NH * NP * HD) {
        int d = idx & 63;
        int p = (idx >> 6) % NP;
        int h = idx / (NP * HD);
        g_relT[idx] = E[(size_t)p * DIMM + d * NH + h];
    }
}

// ---------------------------------------------------------------------------
// qrel[b,h,s,p] = sum_d q[b,h,s,d] * relT[h,p,d]   (scalar, small)
// ---------------------------------------------------------------------------
__global__ __launch_bounds__(256) void qrel_kernel(const float* __restrict__ Qp)
{
    __shared__ float QsT[64][68];
    __shared__ float RsT[64][68];

    const int i0 = blockIdx.x * 64;
    const int h = blockIdx.y, b = blockIdx.z;
    const int tid = threadIdx.x, tx = tid & 15, ty = tid >> 4;

    const size_t qbase = ((size_t)b * SEQ) * DIMM + h * HD;
    for (int idx = tid; idx < 64 * 64; idx += 256) {
        int r = idx >> 6, d = idx & 63;
        QsT[d][r] = Qp[qbase + (size_t)(i0 + r) * DIMM + d];
    }

    float* orow = g_qrel + (((size_t)b * NH + h) * SEQ + i0) * NP;

    for (int p0 = 0; p0 < NP; p0 += 64) {
        __syncthreads();
        for (int idx = tid; idx < 64 * 64; idx += 256) {
            int pp = idx >> 6, d = idx & 63;
            int p = p0 + pp;
            RsT[d][pp] = (p < NP) ? g_relT[((size_t)h * NP + p) * HD + d] : 0.f;
        }
        __syncthreads();

        ull acc[4][2];
        #pragma unroll
        for (int i = 0; i < 4; i++) { acc[i][0] = 0ull; acc[i][1] = 0ull; }

        #pragma unroll 16
        for (int d = 0; d < 64; d++) {
            float4 a4 = *(const float4*)&QsT[d][ty * 4];
            float4 b4 = *(const float4*)&RsT[d][tx * 4];
            ull bp0 = pack2(b4.x, b4.y), bp1 = pack2(b4.z, b4.w);
            float a[4] = {a4.x, a4.y, a4.z, a4.w};
            #pragma unroll
            for (int i = 0; i < 4; i++) {
                ull ap = pack2(a[i], a[i]);
                acc[i][0] = fma2(ap, bp0, acc[i][0]);
                acc[i][1] = fma2(ap, bp1, acc[i][1]);
            }
        }

        #pragma unroll
        for (int i = 0; i < 4; i++) {
            float2 c0 = unpack2(acc[i][0]), c1 = unpack2(acc[i][1]);
            float cv[4] = {c0.x, c0.y, c1.x, c1.y};
            #pragma unroll
            for (int j = 0; j < 4; j++) {
                int p = p0 + tx * 4 + j;
                if (p < NP)
                    orow[(size_t)(ty * 4 + i) * NP + p] = cv[j];
            }
        }
    }
}

// ---------------------------------------------------------------------------
// Tensor-core banded flash attention (FA2 layout, bf16 hi/lo split math).
// 64 queries/block, 4 warps (m16 each), 64-key chunks, cp.async double buffer.
// ---------------------------------------------------------------------------
#define ROWV 144                         // 64 bf16 (128B) + 16B pad
#define ATILE (64 * ROWV)                // 9216
#define AQH 0
#define AQL ATILE
#define AKV (2 * ATILE)                  // start of K/V double buffers
#define KVSTG (4 * ATILE)                // Kh,Kl,Vh,Vl per buffer = 36864
#define ATT_SMEM (2 * ATILE + 2 * KVSTG) // 92160

__device__ __forceinline__ void attn_load_kv(
    uint32_t sb, int buf, size_t gbase, int j0,
    const __nv_bfloat16* __restrict__ KH, const __nv_bfloat16* __restrict__ KL,
    const __nv_bfloat16* __restrict__ VH, const __nv_bfloat16* __restrict__ VL,
    int tid)
{
    const uint32_t dst = sb + AKV + (uint32_t)buf * KVSTG;
    const __nv_bfloat16* srcs[4] = {KH, KL, VH, VL};
    #pragma unroll
    for (int t = 0; t < 4; t++) {
        const __nv_bfloat16* src = srcs[t];
        #pragma unroll
        for (int i = 0; i < 4; i++) {
            const int c = tid + i * 128;           // 0..511
            const int row = c >> 3, cg = c & 7;
            const uint32_t sa = dst + (uint32_t)t * ATILE + row * ROWV + cg * 16;
            const void* ga = src + gbase + (size_t)(j0 + row) * DIMM + cg * 8;
            CP_ASYNC16(sa, ga);
        }
    }
    CP_COMMIT();
}

__global__ __launch_bounds__(128, 1) void attn_tc_kernel(
    const __nv_bfloat16* __restrict__ QH, const __nv_bfloat16* __restrict__ QL,
    const __nv_bfloat16* __restrict__ KH, const __nv_bfloat16* __restrict__ KL,
    const __nv_bfloat16* __restrict__ VH, const __nv_bfloat16* __restrict__ VL,
    __nv_bfloat16* __restrict__ CXH, __nv_bfloat16* __restrict__ CXL)
{
    extern __shared__ __align__(128) char sm[];
    const uint32_t sb = smem_u32(sm);

    const int i0 = blockIdx.x * 64;
    const int h = blockIdx.y, b = blockIdx.z;
    const int tid = threadIdx.x, lane = tid & 31, wm = tid >> 5;

    const size_t base = ((size_t)b * SEQ) * DIMM + h * HD;
    const float* qrl = g_qrel + (((size_t)b * NH + h) * SEQ) * NP;

    const int jstart = (i0 - RADIUS) < 0 ? 0 : (i0 - RADIUS);
    const int jend   = (i0 + 64 + RADIUS) > SEQ ? SEQ : (i0 + 64 + RADIUS);
    const int nchunk = (jend - jstart) >> 6;

    // load Q (hi/lo) + first K/V chunk
    #pragma unroll
    for (int i = 0; i < 4; i++) {
        const int c = tid + i * 128;
        const int row = c >> 3, cg = c & 7;
        const uint32_t sa = sb + row * ROWV + cg * 16;
        const size_t ga = base + (size_t)(i0 + row) * DIMM + cg * 8;
        CP_ASYNC16(sa, (const void*)(QH + ga));
        CP_ASYNC16(sa + ATILE, (const void*)(QL + ga));
    }
    attn_load_kv(sb, 0, base, jstart, KH, KL, VH, VL, tid);

    float of[8][4];
    #pragma unroll
    for (int f = 0; f < 8; f++)
        #pragma unroll
        for (int r = 0; r < 4; r++) of[f][r] = 0.f;
    float mrow[2] = {-1e30f, -1e30f};
    float lrow[2] = {0.f, 0.f};

    const int gi0 = i0 + wm * 16 + (lane >> 2);    // row 0 (row 1 = +8)
    const uint32_t qa_lane = (uint32_t)((wm * 16 + (lane & 15)) * ROWV + (lane >> 4) * 16);

    for (int ch = 0; ch < nchunk; ch++) {
        const int j0 = jstart + ch * 64;
        if (ch + 1 < nchunk) {
            attn_load_kv(sb, (ch + 1) & 1, base, j0 + 64, KH, KL, VH, VL, tid);
            CP_WAIT(1);
        } else {
            CP_WAIT(0);
        }
        __syncthreads();

        const uint32_t kvb = sb + AKV + (uint32_t)(ch & 1) * KVSTG;

        // ---- S = Q K^T (3-term split) ----
        float sf[8][4];
        #pragma unroll
        for (int f = 0; f < 8; f++)
            #pragma unroll
            for (int r = 0; r < 4; r++) sf[f][r] = 0.f;

        #pragma unroll
        for (int kst = 0; kst < 4; kst++) {
            uint32_t aqh[4], aql[4];
            const uint32_t qaddr = sb + qa_lane + kst * 32;
            LDSM4(aqh, qaddr);
            LDSM4(aql, qaddr + ATILE);
            #pragma unroll
            for (int g = 0; g < 4; g++) {
                const uint32_t kaddr = kvb + (uint32_t)((g * 16 + (lane & 15)) * ROWV
                                     + kst * 32 + (lane >> 4) * 16);
                uint32_t bh[4], bl[4];
                LDSM4(bh, kaddr);
                LDSM4(bl, kaddr + ATILE);
                MMA16816(sf[2 * g],     aqh, bh[0], bh[2]);
                MMA16816(sf[2 * g],     aqh, bl[0], bl[2]);
                MMA16816(sf[2 * g],     aql, bh[0], bh[2]);
                MMA16816(sf[2 * g + 1], aqh, bh[1], bh[3]);
                MMA16816(sf[2 * g + 1], aqh, bl[1], bl[3]);
                MMA16816(sf[2 * g + 1], aql, bh[1], bh[3]);
            }
        }

        // ---- bias + mask + scale ----
        #pragma unroll
        for (int f = 0; f < 8; f++) {
            const int gj0 = j0 + f * 8 + (lane & 3) * 2;
            #pragma unroll
            for (int e = 0; e < 4; e++) {
                const int gi = gi0 + (e >> 1) * 8;
                const int gj = gj0 + (e & 1);
                const int dl = gj - gi;
                if (dl > RADIUS || dl < -RADIUS) {
                    sf[f][e] = -1e30f;
                } else {
                    int p = dl; if (p > RREL) p = RREL; if (p < -RREL) p = -RREL;
                    sf[f][e] = (sf[f][e] + __ldg(&qrl[(size_t)gi * NP + p + RREL])) * 0.125f;
                }
            }
        }

        // ---- online softmax ----
        float mloc[2] = {-1e30f, -1e30f};
        #pragma unroll
        for (int f = 0; f < 8; f++) {
            mloc[0] = fmaxf(mloc[0], fmaxf(sf[f][0], sf[f][1]));
            mloc[1] = fmaxf(mloc[1], fmaxf(sf[f][2], sf[f][3]));
        }
        #pragma unroll
        for (int off = 1; off <= 2; off <<= 1) {
            mloc[0] = fmaxf(mloc[0], __shfl_xor_sync(0xffffffffu, mloc[0], off));
            mloc[1] = fmaxf(mloc[1], __shfl_xor_sync(0xffffffffu, mloc[1], off));
        }
        float mnew[2], scl[2];
        #pragma unroll
        for (int r = 0; r < 2; r++) {
            mnew[r] = fmaxf(mrow[r], mloc[r]);
            scl[r] = __expf(mrow[r] - mnew[r]);
            mrow[r] = mnew[r];
        }

        float ls[2] = {0.f, 0.f};
        #pragma unroll
        for (int f = 0; f < 8; f++) {
            sf[f][0] = __expf(sf[f][0] - mnew[0]);
            sf[f][1] = __expf(sf[f][1] - mnew[0]);
            sf[f][2] = __expf(sf[f][2] - mnew[1]);
            sf[f][3] = __expf(sf[f][3] - mnew[1]);
            ls[0] += sf[f][0] + sf[f][1];
            ls[1] += sf[f][2] + sf[f][3];
        }
        #pragma unroll
        for (int off = 1; off <= 2; off <<= 1) {
            ls[0] += __shfl_xor_sync(0xffffffffu, ls[0], off);
            ls[1] += __shfl_xor_sync(0xffffffffu, ls[1], off);
        }
        lrow[0] = lrow[0] * scl[0] + ls[0];
        lrow[1] = lrow[1] * scl[1] + ls[1];
        #pragma unroll
        for (int f = 0; f < 8; f++) {
            of[f][0] *= scl[0]; of[f][1] *= scl[0];
            of[f][2] *= scl[1]; of[f][3] *= scl[1];
        }

        // ---- P -> bf16 hi/lo A-fragments (C-frag == A-frag identity) ----
        uint32_t pah[4][4], pal[4][4];
        #pragma unroll
        for (int t = 0; t < 4; t++) {
            #pragma unroll
            for (int half = 0; half < 2; half++) {       // frag 2t, 2t+1
                const float* s4 = sf[2 * t + half];
                #pragma unroll
                for (int rr = 0; rr < 2; rr++) {         // rowlo/rowhi pair
                    float x0 = s4[rr * 2], x1 = s4[rr * 2 + 1];
                    __nv_bfloat162 h2 = __float22bfloat162_rn(make_float2(x0, x1));
                    float2 back = __bfloat1622float2(h2);
                    __nv_bfloat162 l2 = __float22bfloat162_rn(
                        make_float2(x0 - back.x, x1 - back.y));
                    pah[t][half * 2 + rr] = *(uint32_t*)&h2;
                    pal[t][half * 2 + rr] = *(uint32_t*)&l2;
                }
            }
        }

        // ---- O += P V (3-term split), V via ldmatrix.trans ----
        #pragma unroll
        for (int t = 0; t < 4; t++) {
            #pragma unroll
            for (int vg = 0; vg < 4; vg++) {
                const uint32_t vaddr = kvb + 2u * ATILE
                    + (uint32_t)((t * 16 + (lane & 15)) * ROWV + vg * 32 + (lane >> 4) * 16);
                uint32_t vh[4], vl[4];
                LDSM4T(vh, vaddr);
                LDSM4T(vl, vaddr + ATILE);
                MMA16816(of[2 * vg],     pah[t], vh[0], vh[1]);
                MMA16816(of[2 * vg],     pah[t], vl[0], vl[1]);
                MMA16816(of[2 * vg],     pal[t], vh[0], vh[1]);
                MMA16816(of[2 * vg + 1], pah[t], vh[2], vh[3]);
                MMA16816(of[2 * vg + 1], pah[t], vl[2], vl[3]);
                MMA16816(of[2 * vg + 1], pal[t], vh[2], vh[3]);
            }
        }
        __syncthreads();
    }

    // ---- epilogue: O /= l, write bf16 hi/lo ctx ----
    const float inv0 = 1.f / lrow[0], inv1 = 1.f / lrow[1];
    #pragma unroll
    for (int f = 0; f < 8; f++) {
        const int col = f * 8 + (lane & 3) * 2;
        #pragma unroll
        for (int rr = 0; rr < 2; rr++) {
            const int gi = gi0 + rr * 8;
            const float inv = rr ? inv1 : inv0;
            float x0 = of[f][rr * 2] * inv, x1 = of[f][rr * 2 + 1] * inv;
            __nv_bfloat162 h2 = __float22bfloat162_rn(make_float2(x0, x1));
            float2 back = __bfloat1622float2(h2);
            __nv_bfloat162 l2 = __float22bfloat162_rn(
                make_float2(x0 - back.x, x1 - back.y));
            const size_t off = base + (size_t)gi * DIMM + col;
            *(__nv_bfloat162*)&CXH[off] = h2;
            *(__nv_bfloat162*)&CXL[off] = l2;
        }
    }
}

// ---------------------------------------------------------------------------
// Launch
// ---------------------------------------------------------------------------
extern "C" void kernel_launch(void* const* d_in, const int* in_sizes, int n_in,
                              void* d_out, int out_size)
{
    const float* Q  = (const float*)d_in[0];
    const float* K  = (const float*)d_in[1];
    const float* V  = (const float*)d_in[2];
    const float* Wq = (const float*)d_in[3];
    const float* Wk = (const float*)d_in[4];
    const float* Wv = (const float*)d_in[5];
    const float* Wo = (const float*)d_in[6];
    const float* E  = (const float*)d_in[7];
    float* out = (float*)d_out;

    float* q;
    cudaGetSymbolAddress((void**)&q, g_q);

    __nv_bfloat16 *qih, *qil, *kih, *kil, *vih, *vil;
    __nv_bfloat16 *qph, *qpl, *kph, *kpl, *vph, *vpl, *cxh, *cxl;
    __nv_bfloat16 *wqh, *wql, *wkh, *wkl, *wvh, *wvl, *woh, *wol;
    cudaGetSymbolAddress((void**)&qih, g_qin_h); cudaGetSymbolAddress((void**)&qil, g_qin_l);
    cudaGetSymbolAddress((void**)&kih, g_kin_h); cudaGetSymbolAddress((void**)&kil, g_kin_l);
    cudaGetSymbolAddress((void**)&vih, g_vin_h); cudaGetSymbolAddress((void**)&vil, g_vin_l);
    cudaGetSymbolAddress((void**)&qph, g_qp_h);  cudaGetSymbolAddress((void**)&qpl, g_qp_l);
    cudaGetSymbolAddress((void**)&kph, g_kp_h);  cudaGetSymbolAddress((void**)&kpl, g_kp_l);
    cudaGetSymbolAddress((void**)&vph, g_vp_h);  cudaGetSymbolAddress((void**)&vpl, g_vp_l);
    cudaGetSymbolAddress((void**)&cxh, g_ctx_h); cudaGetSymbolAddress((void**)&cxl, g_ctx_l);
    cudaGetSymbolAddress((void**)&wqh, g_wq_h);  cudaGetSymbolAddress((void**)&wql, g_wq_l);
    cudaGetSymbolAddress((void**)&wkh, g_wk_h);  cudaGetSymbolAddress((void**)&wkl, g_wk_l);
    cudaGetSymbolAddress((void**)&wvh, g_wv_h);  cudaGetSymbolAddress((void**)&wvl, g_wv_l);
    cudaGetSymbolAddress((void**)&woh, g_wo_h);  cudaGetSymbolAddress((void**)&wol, g_wo_l);

    static bool attr_set = false;
    if (!attr_set) {
        cudaFuncSetAttribute(gemm_hmma, cudaFuncAttributeMaxDynamicSharedMemorySize, GEMM_SMEM);
        cudaFuncSetAttribute(attn_tc_kernel, cudaFuncAttributeMaxDynamicSharedMemorySize, ATT_SMEM);
        attr_set = true;
    }

    const int M = BATCH * SEQ;             // 4096
    dim3 tc_grid(DIMM / 128, M / 128);     // (8, 32)

    split_kernel<<<NELEM / 256, 256>>>(Q, qih, qil, NELEM);
    split_kernel<<<NELEM / 256, 256>>>(K, kih, kil, NELEM);
    split_kernel<<<NELEM / 256, 256>>>(V, vih, vil, NELEM);
    split_kernel<<<(DIMM * DIMM) / 256, 256>>>(Wq, wqh, wql, DIMM * DIMM);
    split_kernel<<<(DIMM * DIMM) / 256, 256>>>(Wk, wkh, wkl, DIMM * DIMM);
    split_kernel<<<(DIMM * DIMM) / 256, 256>>>(Wv, wvh, wvl, DIMM * DIMM);
    wop_split_kernel<<<(DIMM * DIMM) / 256, 256>>>(Wo);
    relT_kernel<<<(NH * NP * HD + 255) / 256, 256>>>(E);

    // projections: q (fp32 + splits), k/v (splits only)
    gemm_hmma<<<tc_grid, 256, GEMM_SMEM>>>(qih, qil, wqh, wql, q, qph, qpl, M, DIMM, DIMM);
    gemm_hmma<<<tc_grid, 256, GEMM_SMEM>>>(kih, kil, wkh, wkl, nullptr, kph, kpl, M, DIMM, DIMM);
    gemm_hmma<<<tc_grid, 256, GEMM_SMEM>>>(vih, vil, wvh, wvl, nullptr, vph, vpl, M, DIMM, DIMM);

    qrel_kernel<<<dim3(SEQ / 64, NH, BATCH), 256>>>(q);
    attn_tc_kernel<<<dim3(SEQ / 64, NH, BATCH), 128, ATT_SMEM>>>(
        qph, qpl, kph, kpl, vph, vpl, cxh, cxl);

    gemm_hmma<<<tc_grid, 256, GEMM_SMEM>>>(cxh, cxl, woh, wol, out, nullptr, nullptr, M, DIMM, DIMM);
}

// round 6
// speedup vs baseline: 2.2627x; 1.1353x over previous
#include <cuda_runtime.h>
#include <cuda_bf16.h>
#include <cstdint>

// Problem constants
#define BATCH 2
#define SEQ   2048
#define DIMM  1024
#define NH    16
#define HD    64
#define NP    257
#define RREL  128
#define RADIUS 256
#define NELEM (BATCH * SEQ * DIMM)   // 4194304

typedef unsigned long long ull;

// ---------------------------------------------------------------------------
// f32x2 helpers (qrel kernel)
// ---------------------------------------------------------------------------
__device__ __forceinline__ ull pack2(float x, float y) {
    ull r; asm("mov.b64 %0, {%1, %2};" : "=l"(r) : "f"(x), "f"(y)); return r;
}
__device__ __forceinline__ float2 unpack2(ull v) {
    float2 r; asm("mov.b64 {%0, %1}, %2;" : "=f"(r.x), "=f"(r.y) : "l"(v)); return r;
}
__device__ __forceinline__ ull fma2(ull a, ull b, ull c) {
    ull d; asm("fma.rn.f32x2 %0, %1, %2, %3;" : "=l"(d) : "l"(a), "l"(b), "l"(c)); return d;
}

// ---------------------------------------------------------------------------
// Tensor-core (mma.sync, arch-portable) helpers
// ---------------------------------------------------------------------------
__device__ __forceinline__ uint32_t smem_u32(const void* p) {
    uint32_t a;
    asm("{ .reg .u64 t; cvta.to.shared.u64 t, %1; cvt.u32.u64 %0, t; }" : "=r"(a) : "l"(p));
    return a;
}

#define LDSM4(r, addr) \
    asm volatile("ldmatrix.sync.aligned.m8n8.x4.shared.b16 {%0,%1,%2,%3}, [%4];" \
        : "=r"((r)[0]), "=r"((r)[1]), "=r"((r)[2]), "=r"((r)[3]) : "r"(addr))

#define LDSM4T(r, addr) \
    asm volatile("ldmatrix.sync.aligned.m8n8.x4.trans.shared.b16 {%0,%1,%2,%3}, [%4];" \
        : "=r"((r)[0]), "=r"((r)[1]), "=r"((r)[2]), "=r"((r)[3]) : "r"(addr))

#define MMA16816(d, a, b0, b1) \
    asm volatile("mma.sync.aligned.m16n8k16.row.col.f32.bf16.bf16.f32 " \
        "{%0,%1,%2,%3}, {%4,%5,%6,%7}, {%8,%9}, {%0,%1,%2,%3};" \
        : "+f"((d)[0]), "+f"((d)[1]), "+f"((d)[2]), "+f"((d)[3]) \
        : "r"((a)[0]), "r"((a)[1]), "r"((a)[2]), "r"((a)[3]), "r"(b0), "r"(b1))

#define CP_ASYNC16(sa, ga) \
    asm volatile("cp.async.cg.shared.global [%0], [%1], 16;" :: "r"(sa), "l"(ga))
#define CP_COMMIT() asm volatile("cp.async.commit_group;" ::: "memory")
#define CP_WAIT(n)  asm volatile("cp.async.wait_group %0;" :: "n"(n) : "memory")

// ---------------------------------------------------------------------------
// Device scratch
// ---------------------------------------------------------------------------
__device__ float g_q[NELEM];                              // projected q fp32 (for qrel)
__device__ float g_relT[NH * NP * HD];
__device__ float g_qrel[(size_t)BATCH * NH * SEQ * NP];

__device__ __nv_bfloat16 g_qin_h[NELEM], g_qin_l[NELEM];
__device__ __nv_bfloat16 g_kin_h[NELEM], g_kin_l[NELEM];
__device__ __nv_bfloat16 g_vin_h[NELEM], g_vin_l[NELEM];
__device__ __nv_bfloat16 g_qp_h[NELEM],  g_qp_l[NELEM];   // projected splits
__device__ __nv_bfloat16 g_kp_h[NELEM],  g_kp_l[NELEM];
__device__ __nv_bfloat16 g_vp_h[NELEM],  g_vp_l[NELEM];
__device__ __nv_bfloat16 g_ctx_h[NELEM], g_ctx_l[NELEM];
__device__ __nv_bfloat16 g_wq_h[DIMM * DIMM], g_wq_l[DIMM * DIMM];
__device__ __nv_bfloat16 g_wk_h[DIMM * DIMM], g_wk_l[DIMM * DIMM];
__device__ __nv_bfloat16 g_wv_h[DIMM * DIMM], g_wv_l[DIMM * DIMM];
__device__ __nv_bfloat16 g_wo_h[DIMM * DIMM], g_wo_l[DIMM * DIMM];

// ---------------------------------------------------------------------------
// Merged input split: Q/K/V fp32 -> bf16 hi/lo, vectorized float4.
// grid (NELEM/1024, 3)
// ---------------------------------------------------------------------------
__global__ void split_in_kernel(const float* __restrict__ Q,
                                const float* __restrict__ K,
                                const float* __restrict__ V)
{
    const int t = blockIdx.y;
    const float* src = (t == 0) ? Q : (t == 1) ? K : V;
    __nv_bfloat16* hi = (t == 0) ? g_qin_h : (t == 1) ? g_kin_h : g_vin_h;
    __nv_bfloat16* lo = (t == 0) ? g_qin_l : (t == 1) ? g_kin_l : g_vin_l;

    const int i4 = (blockIdx.x * 256 + threadIdx.x) * 4;
    float4 x = *(const float4*)(src + i4);

    __nv_bfloat162 h0 = __float22bfloat162_rn(make_float2(x.x, x.y));
    __nv_bfloat162 h1 = __float22bfloat162_rn(make_float2(x.z, x.w));
    float2 b0 = __bfloat1622float2(h0), b1 = __bfloat1622float2(h1);
    __nv_bfloat162 l0 = __float22bfloat162_rn(make_float2(x.x - b0.x, x.y - b0.y));
    __nv_bfloat162 l1 = __float22bfloat162_rn(make_float2(x.z - b1.x, x.w - b1.y));

    *(uint2*)(hi + i4) = make_uint2(*(uint32_t*)&h0, *(uint32_t*)&h1);
    *(uint2*)(lo + i4) = make_uint2(*(uint32_t*)&l0, *(uint32_t*)&l1);
}

// ---------------------------------------------------------------------------
// Merged weight split (Wq/Wk/Wv plain, Wo permuted). grid (DIMM*DIMM/256, 4)
// ---------------------------------------------------------------------------
__global__ void split_w_kernel(const float* __restrict__ Wq,
                               const float* __restrict__ Wk,
                               const float* __restrict__ Wv,
                               const float* __restrict__ Wo)
{
    const int t = blockIdx.y;
    const int idx = blockIdx.x * 256 + threadIdx.x;

    float x;
    __nv_bfloat16 *hi, *lo;
    if (t == 3) {
        const int k = idx & 1023, n = idx >> 10;
        x = Wo[(size_t)n * DIMM + (k & 63) * NH + (k >> 6)];
        hi = g_wo_h; lo = g_wo_l;
    } else {
        const float* src = (t == 0) ? Wq : (t == 1) ? Wk : Wv;
        x = src[idx];
        hi = (t == 0) ? g_wq_h : (t == 1) ? g_wk_h : g_wv_h;
        lo = (t == 0) ? g_wq_l : (t == 1) ? g_wk_l : g_wv_l;
    }
    __nv_bfloat16 h = __float2bfloat16(x);
    hi[idx] = h;
    lo[idx] = __float2bfloat16(x - __bfloat162float(h));
}

// ---------------------------------------------------------------------------
// Warp-MMA split GEMM (batched over blockIdx.z pointer sets).
// ---------------------------------------------------------------------------
#define BKB 32
#define NSTG (DIMM / BKB)            // 32
#define ROWB 80
#define TILE_B (128 * ROWB)
#define STG_B (4 * TILE_B)
#define GEMM_SMEM (2 * STG_B)        // 81920

struct GemmSet {
    const __nv_bfloat16 *Ah, *Al, *Bh, *Bl;
    float* C;
    __nv_bfloat16 *CH, *CL;
};
struct GemmSet3 { GemmSet s[3]; };

__device__ __forceinline__ void gemm_load_stage(
    uint32_t sbase, int s, int m0, int n0,
    const __nv_bfloat16* __restrict__ Ah, const __nv_bfloat16* __restrict__ Al,
    const __nv_bfloat16* __restrict__ Bh, const __nv_bfloat16* __restrict__ Bl,
    int K, int tid)
{
    const int k0 = s * BKB;
    const uint32_t dst = sbase + (uint32_t)(s & 1) * STG_B;
    const __nv_bfloat16* srcs[4] = {Ah, Al, Bh, Bl};
    #pragma unroll
    for (int t = 0; t < 4; t++) {
        const __nv_bfloat16* src = srcs[t];
        const int r0 = (t < 2) ? m0 : n0;
        #pragma unroll
        for (int rep = 0; rep < 2; rep++) {
            const int c = tid + rep * 256;
            const int row = c >> 2, ch = c & 3;
            const uint32_t sa = dst + (uint32_t)t * TILE_B + row * ROWB + ch * 16;
            const void* ga = src + (size_t)(r0 + row) * K + k0 + ch * 8;
            CP_ASYNC16(sa, ga);
        }
    }
    CP_COMMIT();
}

__global__ __launch_bounds__(256, 2) void gemm_hmma(
    GemmSet3 sets, int M, int N, int K)
{
    extern __shared__ __align__(128) char sm[];
    const uint32_t sbase = smem_u32(sm);

    const GemmSet p = sets.s[blockIdx.z];
    const __nv_bfloat16* __restrict__ Ah = p.Ah;
    const __nv_bfloat16* __restrict__ Al = p.Al;
    const __nv_bfloat16* __restrict__ Bh = p.Bh;
    const __nv_bfloat16* __restrict__ Bl = p.Bl;

    const int tid = threadIdx.x, lane = tid & 31, wid = tid >> 5;
    const int wm = wid >> 1, wn = wid & 1;
    const int m0 = blockIdx.y * 128, n0 = blockIdx.x * 128;

    float acc[2][8][4];
    #pragma unroll
    for (int i = 0; i < 2; i++)
        #pragma unroll
        for (int j = 0; j < 8; j++)
            #pragma unroll
            for (int r = 0; r < 4; r++) acc[i][j][r] = 0.f;

    gemm_load_stage(sbase, 0, m0, n0, Ah, Al, Bh, Bl, K, tid);

    const uint32_t a_lane = (uint32_t)((wm * 32 + (lane & 15)) * ROWB + (lane >> 4) * 16);
    const uint32_t b_lane = (uint32_t)((wn * 64 + (lane & 15)) * ROWB + (lane >> 4) * 16)
                          + 2u * TILE_B;

    for (int s = 0; s < NSTG; s++) {
        if (s + 1 < NSTG) {
            gemm_load_stage(sbase, s + 1, m0, n0, Ah, Al, Bh, Bl, K, tid);
            CP_WAIT(1);
        } else {
            CP_WAIT(0);
        }
        __syncthreads();

        const uint32_t st = sbase + (uint32_t)(s & 1) * STG_B;

        #pragma unroll
        for (int kk = 0; kk < 2; kk++) {
            uint32_t ah[2][4], al[2][4];
            #pragma unroll
            for (int mi = 0; mi < 2; mi++) {
                const uint32_t aaddr = st + a_lane + (uint32_t)(mi * 16 * ROWB) + kk * 32;
                LDSM4(ah[mi], aaddr);
                LDSM4(al[mi], aaddr + TILE_B);
            }
            #pragma unroll
            for (int g = 0; g < 4; g++) {
                const uint32_t baddr = st + b_lane + (uint32_t)(g * 16 * ROWB) + kk * 32;
                uint32_t bh[4], bl[4];
                LDSM4(bh, baddr);
                LDSM4(bl, baddr + TILE_B);
                #pragma unroll
                for (int mi = 0; mi < 2; mi++) {
                    MMA16816(acc[mi][2 * g],     ah[mi], bh[0], bh[2]);
                    MMA16816(acc[mi][2 * g],     ah[mi], bl[0], bl[2]);
                    MMA16816(acc[mi][2 * g],     al[mi], bh[0], bh[2]);
                    MMA16816(acc[mi][2 * g + 1], ah[mi], bh[1], bh[3]);
                    MMA16816(acc[mi][2 * g + 1], ah[mi], bl[1], bl[3]);
                    MMA16816(acc[mi][2 * g + 1], al[mi], bh[1], bh[3]);
                }
            }
        }
        __syncthreads();
    }

    #pragma unroll
    for (int mi = 0; mi < 2; mi++) {
        const int row = m0 + wm * 32 + mi * 16 + (lane >> 2);
        #pragma unroll
        for (int nj = 0; nj < 8; nj++) {
            const int col = n0 + wn * 64 + nj * 8 + (lane & 3) * 2;
            const float* a = acc[mi][nj];
            if (p.C) {
                *(float2*)&p.C[(size_t)row * N + col] = make_float2(a[0], a[1]);
                *(float2*)&p.C[(size_t)(row + 8) * N + col] = make_float2(a[2], a[3]);
            }
            if (p.CH) {
                #pragma unroll
                for (int hrow = 0; hrow < 2; hrow++) {
                    float x0 = a[hrow * 2], x1 = a[hrow * 2 + 1];
                    __nv_bfloat162 h2 = __float22bfloat162_rn(make_float2(x0, x1));
                    float2 back = __bfloat1622float2(h2);
                    __nv_bfloat162 l2 = __float22bfloat162_rn(
                        make_float2(x0 - back.x, x1 - back.y));
                    const size_t off = (size_t)(row + hrow * 8) * N + col;
                    *(__nv_bfloat162*)&p.CH[off] = h2;
                    *(__nv_bfloat162*)&p.CL[off] = l2;
                }
            }
        }
    }
}

// ---------------------------------------------------------------------------
// relT[h,p,d] = E[p, d*16 + h]
// ---------------------------------------------------------------------------
__global__ void relT_kernel(const float* __restrict__ E)
{
    int idx = blockIdx.x * 256 + threadIdx.x;
    if (idx < NH * NP * HD) {
        int d = idx & 63;
        int p = (idx >> 6) % NP;
        int h = idx / (NP * HD);
        g_relT[idx] = E[(size_t)p * DIMM + d * NH + h];
    }
}

// ---------------------------------------------------------------------------
// qrel[b,h,s,p] = sum_d q[b,h,s,d] * relT[h,p,d]
// ---------------------------------------------------------------------------
__global__ __launch_bounds__(256) void qrel_kernel(const float* __restrict__ Qp)
{
    __shared__ float QsT[64][68];
    __shared__ float RsT[64][68];

    const int i0 = blockIdx.x * 64;
    const int h = blockIdx.y, b = blockIdx.z;
    const int tid = threadIdx.x, tx = tid & 15, ty = tid >> 4;

    const size_t qbase = ((size_t)b * SEQ) * DIMM + h * HD;
    for (int idx = tid; idx < 64 * 64; idx += 256) {
        int r = idx >> 6, d = idx & 63;
        QsT[d][r] = Qp[qbase + (size_t)(i0 + r) * DIMM + d];
    }

    float* orow = g_qrel + (((size_t)b * NH + h) * SEQ + i0) * NP;

    for (int p0 = 0; p0 < NP; p0 += 64) {
        __syncthreads();
        for (int idx = tid; idx < 64 * 64; idx += 256) {
            int pp = idx >> 6, d = idx & 63;
            int p = p0 + pp;
            RsT[d][pp] = (p < NP) ? g_relT[((size_t)h * NP + p) * HD + d] : 0.f;
        }
        __syncthreads();

        ull acc[4][2];
        #pragma unroll
        for (int i = 0; i < 4; i++) { acc[i][0] = 0ull; acc[i][1] = 0ull; }

        #pragma unroll 16
        for (int d = 0; d < 64; d++) {
            float4 a4 = *(const float4*)&QsT[d][ty * 4];
            float4 b4 = *(const float4*)&RsT[d][tx * 4];
            ull bp0 = pack2(b4.x, b4.y), bp1 = pack2(b4.z, b4.w);
            float a[4] = {a4.x, a4.y, a4.z, a4.w};
            #pragma unroll
            for (int i = 0; i < 4; i++) {
                ull ap = pack2(a[i], a[i]);
                acc[i][0] = fma2(ap, bp0, acc[i][0]);
                acc[i][1] = fma2(ap, bp1, acc[i][1]);
            }
        }

        #pragma unroll
        for (int i = 0; i < 4; i++) {
            float2 c0 = unpack2(acc[i][0]), c1 = unpack2(acc[i][1]);
            float cv[4] = {c0.x, c0.y, c1.x, c1.y};
            #pragma unroll
            for (int j = 0; j < 4; j++) {
                int p = p0 + tx * 4 + j;
                if (p < NP)
                    orow[(size_t)(ty * 4 + i) * NP + p] = cv[j];
            }
        }
    }
}

// ---------------------------------------------------------------------------
// Tensor-core banded flash attention (FA2 layout, bf16 hi/lo split math).
// ---------------------------------------------------------------------------
#define ROWV 144                         // 64 bf16 (128B) + 16B pad
#define ATILE (64 * ROWV)                // 9216
#define AKV (2 * ATILE)
#define KVSTG (4 * ATILE)                // 36864
#define ATT_SMEM (2 * ATILE + 2 * KVSTG) // 92160

__device__ __forceinline__ void attn_load_kv(
    uint32_t sb, int buf, size_t gbase, int j0,
    const __nv_bfloat16* __restrict__ KH, const __nv_bfloat16* __restrict__ KL,
    const __nv_bfloat16* __restrict__ VH, const __nv_bfloat16* __restrict__ VL,
    int tid)
{
    const uint32_t dst = sb + AKV + (uint32_t)buf * KVSTG;
    const __nv_bfloat16* srcs[4] = {KH, KL, VH, VL};
    #pragma unroll
    for (int t = 0; t < 4; t++) {
        const __nv_bfloat16* src = srcs[t];
        #pragma unroll
        for (int i = 0; i < 4; i++) {
            const int c = tid + i * 128;
            const int row = c >> 3, cg = c & 7;
            const uint32_t sa = dst + (uint32_t)t * ATILE + row * ROWV + cg * 16;
            const void* ga = src + gbase + (size_t)(j0 + row) * DIMM + cg * 8;
            CP_ASYNC16(sa, ga);
        }
    }
    CP_COMMIT();
}

__global__ __launch_bounds__(128, 1) void attn_tc_kernel(
    const __nv_bfloat16* __restrict__ QH, const __nv_bfloat16* __restrict__ QL,
    const __nv_bfloat16* __restrict__ KH, const __nv_bfloat16* __restrict__ KL,
    const __nv_bfloat16* __restrict__ VH, const __nv_bfloat16* __restrict__ VL,
    __nv_bfloat16* __restrict__ CXH, __nv_bfloat16* __restrict__ CXL)
{
    extern __shared__ __align__(128) char sm[];
    const uint32_t sb = smem_u32(sm);

    const int i0 = blockIdx.x * 64;
    const int h = blockIdx.y, b = blockIdx.z;
    const int tid = threadIdx.x, lane = tid & 31, wm = tid >> 5;

    const size_t base = ((size_t)b * SEQ) * DIMM + h * HD;
    const float* qrl = g_qrel + (((size_t)b * NH + h) * SEQ) * NP;

    const int jstart = (i0 - RADIUS) < 0 ? 0 : (i0 - RADIUS);
    const int jend   = (i0 + 64 + RADIUS) > SEQ ? SEQ : (i0 + 64 + RADIUS);
    const int nchunk = (jend - jstart) >> 6;

    #pragma unroll
    for (int i = 0; i < 4; i++) {
        const int c = tid + i * 128;
        const int row = c >> 3, cg = c & 7;
        const uint32_t sa = sb + row * ROWV + cg * 16;
        const size_t ga = base + (size_t)(i0 + row) * DIMM + cg * 8;
        CP_ASYNC16(sa, (const void*)(QH + ga));
        CP_ASYNC16(sa + ATILE, (const void*)(QL + ga));
    }
    attn_load_kv(sb, 0, base, jstart, KH, KL, VH, VL, tid);

    float of[8][4];
    #pragma unroll
    for (int f = 0; f < 8; f++)
        #pragma unroll
        for (int r = 0; r < 4; r++) of[f][r] = 0.f;
    float mrow[2] = {-1e30f, -1e30f};
    float lrow[2] = {0.f, 0.f};

    const int gi0 = i0 + wm * 16 + (lane >> 2);
    const uint32_t qa_lane = (uint32_t)((wm * 16 + (lane & 15)) * ROWV + (lane >> 4) * 16);

    for (int ch = 0; ch < nchunk; ch++) {
        const int j0 = jstart + ch * 64;
        if (ch + 1 < nchunk) {
            attn_load_kv(sb, (ch + 1) & 1, base, j0 + 64, KH, KL, VH, VL, tid);
            CP_WAIT(1);
        } else {
            CP_WAIT(0);
        }
        __syncthreads();

        const uint32_t kvb = sb + AKV + (uint32_t)(ch & 1) * KVSTG;

        float sf[8][4];
        #pragma unroll
        for (int f = 0; f < 8; f++)
            #pragma unroll
            for (int r = 0; r < 4; r++) sf[f][r] = 0.f;

        #pragma unroll
        for (int kst = 0; kst < 4; kst++) {
            uint32_t aqh[4], aql[4];
            const uint32_t qaddr = sb + qa_lane + kst * 32;
            LDSM4(aqh, qaddr);
            LDSM4(aql, qaddr + ATILE);
            #pragma unroll
            for (int g = 0; g < 4; g++) {
                const uint32_t kaddr = kvb + (uint32_t)((g * 16 + (lane & 15)) * ROWV
                                     + kst * 32 + (lane >> 4) * 16);
                uint32_t bh[4], bl[4];
                LDSM4(bh, kaddr);
                LDSM4(bl, kaddr + ATILE);
                MMA16816(sf[2 * g],     aqh, bh[0], bh[2]);
                MMA16816(sf[2 * g],     aqh, bl[0], bl[2]);
                MMA16816(sf[2 * g],     aql, bh[0], bh[2]);
                MMA16816(sf[2 * g + 1], aqh, bh[1], bh[3]);
                MMA16816(sf[2 * g + 1], aqh, bl[1], bl[3]);
                MMA16816(sf[2 * g + 1], aql, bh[1], bh[3]);
            }
        }

        #pragma unroll
        for (int f = 0; f < 8; f++) {
            const int gj0 = j0 + f * 8 + (lane & 3) * 2;
            #pragma unroll
            for (int e = 0; e < 4; e++) {
                const int gi = gi0 + (e >> 1) * 8;
                const int gj = gj0 + (e & 1);
                const int dl = gj - gi;
                if (dl > RADIUS || dl < -RADIUS) {
                    sf[f][e] = -1e30f;
                } else {
                    int p = dl; if (p > RREL) p = RREL; if (p < -RREL) p = -RREL;
                    sf[f][e] = (sf[f][e] + __ldg(&qrl[(size_t)gi * NP + p + RREL])) * 0.125f;
                }
            }
        }

        float mloc[2] = {-1e30f, -1e30f};
        #pragma unroll
        for (int f = 0; f < 8; f++) {
            mloc[0] = fmaxf(mloc[0], fmaxf(sf[f][0], sf[f][1]));
            mloc[1] = fmaxf(mloc[1], fmaxf(sf[f][2], sf[f][3]));
        }
        #pragma unroll
        for (int off = 1; off <= 2; off <<= 1) {
            mloc[0] = fmaxf(mloc[0], __shfl_xor_sync(0xffffffffu, mloc[0], off));
            mloc[1] = fmaxf(mloc[1], __shfl_xor_sync(0xffffffffu, mloc[1], off));
        }
        float mnew[2], scl[2];
        #pragma unroll
        for (int r = 0; r < 2; r++) {
            mnew[r] = fmaxf(mrow[r], mloc[r]);
            scl[r] = __expf(mrow[r] - mnew[r]);
            mrow[r] = mnew[r];
        }

        float ls[2] = {0.f, 0.f};
        #pragma unroll
        for (int f = 0; f < 8; f++) {
            sf[f][0] = __expf(sf[f][0] - mnew[0]);
            sf[f][1] = __expf(sf[f][1] - mnew[0]);
            sf[f][2] = __expf(sf[f][2] - mnew[1]);
            sf[f][3] = __expf(sf[f][3] - mnew[1]);
            ls[0] += sf[f][0] + sf[f][1];
            ls[1] += sf[f][2] + sf[f][3];
        }
        #pragma unroll
        for (int off = 1; off <= 2; off <<= 1) {
            ls[0] += __shfl_xor_sync(0xffffffffu, ls[0], off);
            ls[1] += __shfl_xor_sync(0xffffffffu, ls[1], off);
        }
        lrow[0] = lrow[0] * scl[0] + ls[0];
        lrow[1] = lrow[1] * scl[1] + ls[1];
        #pragma unroll
        for (int f = 0; f < 8; f++) {
            of[f][0] *= scl[0]; of[f][1] *= scl[0];
            of[f][2] *= scl[1]; of[f][3] *= scl[1];
        }

        uint32_t pah[4][4], pal[4][4];
        #pragma unroll
        for (int t = 0; t < 4; t++) {
            #pragma unroll
            for (int half = 0; half < 2; half++) {
                const float* s4 = sf[2 * t + half];
                #pragma unroll
                for (int rr = 0; rr < 2; rr++) {
                    float x0 = s4[rr * 2], x1 = s4[rr * 2 + 1];
                    __nv_bfloat162 h2 = __float22bfloat162_rn(make_float2(x0, x1));
                    float2 back = __bfloat1622float2(h2);
                    __nv_bfloat162 l2 = __float22bfloat162_rn(
                        make_float2(x0 - back.x, x1 - back.y));
                    pah[t][half * 2 + rr] = *(uint32_t*)&h2;
                    pal[t][half * 2 + rr] = *(uint32_t*)&l2;
                }
            }
        }

        #pragma unroll
        for (int t = 0; t < 4; t++) {
            #pragma unroll
            for (int vg = 0; vg < 4; vg++) {
                const uint32_t vaddr = kvb + 2u * ATILE
                    + (uint32_t)((t * 16 + (lane & 15)) * ROWV + vg * 32 + (lane >> 4) * 16);
                uint32_t vh[4], vl[4];
                LDSM4T(vh, vaddr);
                LDSM4T(vl, vaddr + ATILE);
                MMA16816(of[2 * vg],     pah[t], vh[0], vh[1]);
                MMA16816(of[2 * vg],     pah[t], vl[0], vl[1]);
                MMA16816(of[2 * vg],     pal[t], vh[0], vh[1]);
                MMA16816(of[2 * vg + 1], pah[t], vh[2], vh[3]);
                MMA16816(of[2 * vg + 1], pah[t], vl[2], vl[3]);
                MMA16816(of[2 * vg + 1], pal[t], vh[2], vh[3]);
            }
        }
        __syncthreads();
    }

    const float inv0 = 1.f / lrow[0], inv1 = 1.f / lrow[1];
    #pragma unroll
    for (int f = 0; f < 8; f++) {
        const int col = f * 8 + (lane & 3) * 2;
        #pragma unroll
        for (int rr = 0; rr < 2; rr++) {
            const int gi = gi0 + rr * 8;
            const float inv = rr ? inv1 : inv0;
            float x0 = of[f][rr * 2] * inv, x1 = of[f][rr * 2 + 1] * inv;
            __nv_bfloat162 h2 = __float22bfloat162_rn(make_float2(x0, x1));
            float2 back = __bfloat1622float2(h2);
            __nv_bfloat162 l2 = __float22bfloat162_rn(
                make_float2(x0 - back.x, x1 - back.y));
            const size_t off = base + (size_t)gi * DIMM + col;
            *(__nv_bfloat162*)&CXH[off] = h2;
            *(__nv_bfloat162*)&CXL[off] = l2;
        }
    }
}

// ---------------------------------------------------------------------------
// Launch
// ---------------------------------------------------------------------------
extern "C" void kernel_launch(void* const* d_in, const int* in_sizes, int n_in,
                              void* d_out, int out_size)
{
    const float* Q  = (const float*)d_in[0];
    const float* K  = (const float*)d_in[1];
    const float* V  = (const float*)d_in[2];
    const float* Wq = (const float*)d_in[3];
    const float* Wk = (const float*)d_in[4];
    const float* Wv = (const float*)d_in[5];
    const float* Wo = (const float*)d_in[6];
    const float* E  = (const float*)d_in[7];
    float* out = (float*)d_out;

    float* q;
    cudaGetSymbolAddress((void**)&q, g_q);

    __nv_bfloat16 *qih, *qil, *kih, *kil, *vih, *vil;
    __nv_bfloat16 *qph, *qpl, *kph, *kpl, *vph, *vpl, *cxh, *cxl;
    __nv_bfloat16 *wqh, *wql, *wkh, *wkl, *wvh, *wvl, *woh, *wol;
    cudaGetSymbolAddress((void**)&qih, g_qin_h); cudaGetSymbolAddress((void**)&qil, g_qin_l);
    cudaGetSymbolAddress((void**)&kih, g_kin_h); cudaGetSymbolAddress((void**)&kil, g_kin_l);
    cudaGetSymbolAddress((void**)&vih, g_vin_h); cudaGetSymbolAddress((void**)&vil, g_vin_l);
    cudaGetSymbolAddress((void**)&qph, g_qp_h);  cudaGetSymbolAddress((void**)&qpl, g_qp_l);
    cudaGetSymbolAddress((void**)&kph, g_kp_h);  cudaGetSymbolAddress((void**)&kpl, g_kp_l);
    cudaGetSymbolAddress((void**)&vph, g_vp_h);  cudaGetSymbolAddress((void**)&vpl, g_vp_l);
    cudaGetSymbolAddress((void**)&cxh, g_ctx_h); cudaGetSymbolAddress((void**)&cxl, g_ctx_l);
    cudaGetSymbolAddress((void**)&wqh, g_wq_h);  cudaGetSymbolAddress((void**)&wql, g_wq_l);
    cudaGetSymbolAddress((void**)&wkh, g_wk_h);  cudaGetSymbolAddress((void**)&wkl, g_wk_l);
    cudaGetSymbolAddress((void**)&wvh, g_wv_h);  cudaGetSymbolAddress((void**)&wvl, g_wv_l);
    cudaGetSymbolAddress((void**)&woh, g_wo_h);  cudaGetSymbolAddress((void**)&wol, g_wo_l);

    static bool attr_set = false;
    if (!attr_set) {
        cudaFuncSetAttribute(gemm_hmma, cudaFuncAttributeMaxDynamicSharedMemorySize, GEMM_SMEM);
        cudaFuncSetAttribute(attn_tc_kernel, cudaFuncAttributeMaxDynamicSharedMemorySize, ATT_SMEM);
        attr_set = true;
    }

    const int M = BATCH * SEQ;             // 4096

    // 0: merged input splits (vectorized)
    split_in_kernel<<<dim3(NELEM / 1024, 3), 256>>>(Q, K, V);
    // 1: merged weight splits (incl. Wo permute)
    split_w_kernel<<<dim3((DIMM * DIMM) / 256, 4), 256>>>(Wq, Wk, Wv, Wo);
    // 2: rel embedding permute
    relT_kernel<<<(NH * NP * HD + 255) / 256, 256>>>(E);

    // 3: batched Q/K/V projections
    GemmSet3 qkv;
    qkv.s[0] = {qih, qil, wqh, wql, q,       qph, qpl};
    qkv.s[1] = {kih, kil, wkh, wkl, nullptr, kph, kpl};
    qkv.s[2] = {vih, vil, wvh, wvl, nullptr, vph, vpl};
    gemm_hmma<<<dim3(DIMM / 128, M / 128, 3), 256, GEMM_SMEM>>>(qkv, M, DIMM, DIMM);

    // 4: relative-position logits
    qrel_kernel<<<dim3(SEQ / 64, NH, BATCH), 256>>>(q);
    // 5: banded flash attention (ncu -s 5 lands here)
    attn_tc_kernel<<<dim3(SEQ / 64, NH, BATCH), 128, ATT_SMEM>>>(
        qph, qpl, kph, kpl, vph, vpl, cxh, cxl);

    // 6: output projection
    GemmSet3 og;
    og.s[0] = {cxh, cxl, woh, wol, out, nullptr, nullptr};
    og.s[1] = og.s[0];
    og.s[2] = og.s[0];
    gemm_hmma<<<dim3(DIMM / 128, M / 128, 1), 256, GEMM_SMEM>>>(og, M, DIMM, DIMM);
}